// round 14
// baseline (speedup 1.0000x reference)
#include <cuda_runtime.h>
#include <cuda_bf16.h>
#include <math.h>
#include <stdint.h>

// Problem constants
#define BQ 4
#define LQ 512
#define HQ 1024
#define MQ 128
#define EQ 64
#define NHQ 16
#define RQ 1024
#define DQ 768
#define BLKQ 64
#define CQ 97
#define NKB 12           // D / BLK  (split-K planes)
#define NP (BQ * RQ)     // 4096 pairs
#define NEQ (BQ * EQ)    // 256 distinct entities
#define KTOT 49152       // D * BLK

// -------- scratch (static device globals: allocation-guard safe) ----------
__device__ float g_ent_emb[NEQ * HQ];              // 1 MB
__device__ int   g_cnt[NEQ];
__device__ int   g_list[NEQ * MQ];
__device__ float g_ent_attn[NEQ * NHQ * LQ];       // 8 MB
__device__ __nv_bfloat16 g_hth[NP * LQ];           // 4 MB  ht hi split
__device__ __nv_bfloat16 g_htl[NP * LQ];           // 4 MB  ht lo split
__device__ __nv_bfloat16 g_seqh[BQ * LQ * HQ];     // 4 MB  seq hi
__device__ __nv_bfloat16 g_seql[BQ * LQ * HQ];     // 4 MB  seq lo
__device__ __nv_bfloat16 g_relh[NP * HQ];          // 8 MB  rel hi
__device__ __nv_bfloat16 g_rell[NP * HQ];          // 8 MB  rel lo
__device__ __nv_bfloat16 g_Wsph[2 * HQ * DQ];      // 3 MB  W bottom-half hi (z-major)
__device__ __nv_bfloat16 g_Wspl[2 * HQ * DQ];      // 3 MB  W bottom-half lo
__device__ float g_hv[NP * DQ];                    // 12 MB
__device__ float g_tv[NP * DQ];                    // 12 MB
__device__ float g_entW[2 * NEQ * DQ];             // 1.5 MB
__device__ float g_part[NKB * NP * CQ];            // 19 MB split-K partials
__device__ __nv_bfloat16 g_WbB_h[KTOT * 128];      // 12.6 MB  Wb k-major hi
__device__ __nv_bfloat16 g_WbB_l[KTOT * 128];      // 12.6 MB  Wb k-major lo

// -------- packed f32x2 helpers (used by gemm_ent) ----
typedef unsigned long long u64t;

__device__ __forceinline__ u64t pack2b(float v) {
    u64t r; asm("mov.b64 %0, {%1, %1};" : "=l"(r) : "f"(v)); return r;
}
__device__ __forceinline__ void fma2(u64t& d, u64t a, u64t b) {
    asm("fma.rn.f32x2 %0, %1, %2, %0;" : "+l"(d) : "l"(a), "l"(b));
}
__device__ __forceinline__ float2 unpack2(u64t v) {
    float2 r; asm("mov.b64 {%0, %1}, %2;" : "=f"(r.x), "=f"(r.y) : "l"(v)); return r;
}

// -------- HMMA helpers ----
__device__ __forceinline__ uint32_t smem_u32(const void* p) {
    return (uint32_t)__cvta_generic_to_shared(p);
}
__device__ __forceinline__ void mma16816(float* d, uint32_t a0, uint32_t a1,
                                         uint32_t a2, uint32_t a3,
                                         uint32_t b0, uint32_t b1) {
    asm volatile(
        "mma.sync.aligned.m16n8k16.row.col.f32.bf16.bf16.f32 "
        "{%0,%1,%2,%3}, {%4,%5,%6,%7}, {%8,%9}, {%0,%1,%2,%3};"
        : "+f"(d[0]), "+f"(d[1]), "+f"(d[2]), "+f"(d[3])
        : "r"(a0), "r"(a1), "r"(a2), "r"(a3), "r"(b0), "r"(b1));
}
__device__ __forceinline__ void ldsm2t(uint32_t& r0, uint32_t& r1, uint32_t addr) {
    asm volatile("ldmatrix.sync.aligned.m8n8.x2.trans.shared.b16 {%0,%1}, [%2];"
                 : "=r"(r0), "=r"(r1) : "r"(addr));
}
__device__ __forceinline__ uint32_t bfpack(float lo, float hi) {
    __nv_bfloat162 t = __floats2bfloat162_rn(lo, hi);
    return *(uint32_t*)&t;
}
__device__ __forceinline__ void split2(float a0, float a1, uint32_t& hp, uint32_t& lp) {
    __nv_bfloat16 h0 = __float2bfloat16(a0), h1 = __float2bfloat16(a1);
    hp = (uint32_t)__bfloat16_as_ushort(h0) | ((uint32_t)__bfloat16_as_ushort(h1) << 16);
    lp = bfpack(a0 - __bfloat162float(h0), a1 - __bfloat162float(h1));
}

extern __shared__ char s_dyn[];

// ---------------------------------------------------------------------------
// K0: per (b,e) mention index lists
// ---------------------------------------------------------------------------
__global__ void k_build(const int* __restrict__ labels) {
    int b = blockIdx.x, e = threadIdx.x;
    int c = 0;
    int* lst = g_list + (b * EQ + e) * MQ;
    for (int m = 0; m < MQ; m++)
        if (labels[b * MQ + m] == e) lst[c++] = m;
    g_cnt[b * EQ + e] = c;
}

// ---------------------------------------------------------------------------
// K1: segment logsumexp over mentions -> ent_emb [B,E,H]
// ---------------------------------------------------------------------------
__global__ void k_ent_emb(const float* __restrict__ ent_lhs) {
    int be = blockIdx.x;
    int b = be / EQ;
    __shared__ int s_list[MQ];
    int cnt = g_cnt[be];
    for (int i = threadIdx.x; i < cnt; i += 256) s_list[i] = g_list[be * MQ + i];
    __syncthreads();
    const float* base = ent_lhs + (size_t)b * MQ * HQ;
    for (int h = threadIdx.x; h < HQ; h += 256) {
        float o = 0.f;
        if (cnt > 0) {
            float mx = -3.4e38f;
            for (int i = 0; i < cnt; i++) mx = fmaxf(mx, base[s_list[i] * HQ + h]);
            float s = 0.f;
            for (int i = 0; i < cnt; i++) s += expf(base[s_list[i] * HQ + h] - mx);
            o = mx + logf(s);
        }
        g_ent_emb[be * HQ + h] = o;
    }
}

// ---------------------------------------------------------------------------
// K2: mean mention attention -> ent_attn [B,E,NH,L]
// ---------------------------------------------------------------------------
__global__ void k_ent_attn(const float* __restrict__ attn) {
    int be = blockIdx.y, nh = blockIdx.x;
    int b = be / EQ;
    int cnt = g_cnt[be];
    __shared__ int s_list[MQ];
    for (int i = threadIdx.x; i < cnt; i += 128) s_list[i] = g_list[be * MQ + i];
    __syncthreads();
    float inv = (cnt > 0) ? 1.f / (float)cnt : 0.f;
    const float* abase = attn + ((size_t)(b * NHQ + nh)) * MQ * LQ;
    float* obase = g_ent_attn + ((size_t)(be * NHQ + nh)) * LQ;
    for (int l = threadIdx.x; l < LQ; l += 128) {
        float s = 0.f;
        for (int i = 0; i < cnt; i++) s += abase[s_list[i] * LQ + l];
        obase[l] = s * inv;
    }
}

// ---------------------------------------------------------------------------
// K3: pair attention product, mean over heads, normalize -> bf16 splits
// ---------------------------------------------------------------------------
__global__ void k_ht(const int* __restrict__ hts) {
    int n = blockIdx.x;
    int b = n / RQ;
    int he = hts[n * 2 + 0];
    int te = hts[n * 2 + 1];
    const float* ha = g_ent_attn + ((size_t)(b * EQ + he)) * NHQ * LQ;
    const float* ta = g_ent_attn + ((size_t)(b * EQ + te)) * NHQ * LQ;
    float v[4];
    float loc = 0.f;
#pragma unroll
    for (int rep = 0; rep < 4; rep++) {
        int l = threadIdx.x + rep * 128;
        float acc = 0.f;
#pragma unroll
        for (int nh = 0; nh < NHQ; nh++) acc += ha[nh * LQ + l] * ta[nh * LQ + l];
        v[rep] = acc * (1.0f / NHQ);
        loc += v[rep];
    }
    __shared__ float red[128];
    red[threadIdx.x] = loc;
    __syncthreads();
    for (int s = 64; s > 0; s >>= 1) {
        if (threadIdx.x < s) red[threadIdx.x] += red[threadIdx.x + s];
        __syncthreads();
    }
    float inv = 1.f / (red[0] + 1e-5f);
#pragma unroll
    for (int rep = 0; rep < 4; rep++) {
        int l = threadIdx.x + rep * 128;
        float val = v[rep] * inv;
        __nv_bfloat16 h = __float2bfloat16(val);
        g_hth[(size_t)n * LQ + l] = h;
        g_htl[(size_t)n * LQ + l] = __float2bfloat16(val - __bfloat162float(h));
    }
}

// ---------------------------------------------------------------------------
// K3b/K3c: bf16 hi/lo splits of seq and W bottom halves
// ---------------------------------------------------------------------------
__global__ void k_seqsplit(const float* __restrict__ seq) {
    int idx = blockIdx.x * 256 + threadIdx.x;
    if (idx >= BQ * LQ * HQ) return;
    float w = seq[idx];
    __nv_bfloat16 h = __float2bfloat16(w);
    g_seqh[idx] = h;
    g_seql[idx] = __float2bfloat16(w - __bfloat162float(h));
}

__global__ void k_wsplit(const float* __restrict__ Wh, const float* __restrict__ Wt) {
    int idx = blockIdx.x * 256 + threadIdx.x;
    if (idx >= 2 * HQ * DQ) return;
    int z = idx / (HQ * DQ);
    int r = idx - z * (HQ * DQ);
    float w = (z ? Wt : Wh)[(size_t)(HQ + r / DQ) * DQ + (r % DQ)];
    __nv_bfloat16 h = __float2bfloat16(w);
    g_Wsph[idx] = h;
    g_Wspl[idx] = __float2bfloat16(w - __bfloat162float(h));
}

// ---------------------------------------------------------------------------
// HMMA GEMM tiles: A [128 rows][32 k] pad-40 bf16 hi/lo, B [32 k][128 n]
// pad-136 bf16 hi/lo, double buffered. 8 warps, each 16 rows x 128 cols.
// ---------------------------------------------------------------------------
#define EA_STR 40
#define EB_STR 136
#define EA_SEG (128 * EA_STR)            // 5120 elems
#define EB_SEG (32 * EB_STR)             // 4352 elems
#define HG_SMEM ((4 * EA_SEG + 4 * EB_SEG) * 2)   // 75776 bytes

__device__ __forceinline__ void hg_load(uint4* pfA, uint4* pfB,
        const __nv_bfloat16* Ah_, const __nv_bfloat16* Al_, int astr,
        const __nv_bfloat16* Bh_, const __nv_bfloat16* Bl_, int bstr,
        int p0, int n0, int ks, int tid) {
#pragma unroll
    for (int q = 0; q < 4; q++) {
        int ch = tid + q * 256;          // 0..1023
        int sp = ch >> 9, idx = ch & 511;
        {
            int row = idx >> 2, c8 = idx & 3;
            const __nv_bfloat16* src = (sp ? Al_ : Ah_) +
                (size_t)(p0 + row) * astr + ks * 32 + c8 * 8;
            pfA[q] = *(const uint4*)src;
        }
        {
            int kr = idx >> 4, c8 = idx & 15;
            const __nv_bfloat16* src = (sp ? Bl_ : Bh_) +
                (size_t)(ks * 32 + kr) * bstr + n0 + c8 * 8;
            pfB[q] = *(const uint4*)src;
        }
    }
}

__device__ __forceinline__ void hg_store(const uint4* pfA, const uint4* pfB,
        __nv_bfloat16* As, __nv_bfloat16* Bs, int st, int tid) {
#pragma unroll
    for (int q = 0; q < 4; q++) {
        int ch = tid + q * 256;
        int sp = ch >> 9, idx = ch & 511;
        {
            int row = idx >> 2, c8 = idx & 3;
            *(uint4*)(As + (st * 2 + sp) * EA_SEG + row * EA_STR + c8 * 8) = pfA[q];
        }
        {
            int kr = idx >> 4, c8 = idx & 15;
            *(uint4*)(Bs + (st * 2 + sp) * EB_SEG + kr * EB_STR + c8 * 8) = pfB[q];
        }
    }
}

__device__ __forceinline__ void hg_compute(float* acc, const __nv_bfloat16* As,
        __nv_bfloat16* Bs, int st, int rA, int rB, int ko, int lane) {
    const __nv_bfloat16* Ah = As + (st * 2 + 0) * EA_SEG;
    const __nv_bfloat16* Al = As + (st * 2 + 1) * EA_SEG;
    uint32_t bh_base = smem_u32(Bs + (st * 2 + 0) * EB_SEG);
    uint32_t bl_base = smem_u32(Bs + (st * 2 + 1) * EB_SEG);
#pragma unroll
    for (int kc = 0; kc < 32; kc += 16) {
        uint32_t ah0 = *(const uint32_t*)(Ah + rA * EA_STR + kc + ko);
        uint32_t ah1 = *(const uint32_t*)(Ah + rB * EA_STR + kc + ko);
        uint32_t ah2 = *(const uint32_t*)(Ah + rA * EA_STR + kc + 8 + ko);
        uint32_t ah3 = *(const uint32_t*)(Ah + rB * EA_STR + kc + 8 + ko);
        uint32_t al0 = *(const uint32_t*)(Al + rA * EA_STR + kc + ko);
        uint32_t al1 = *(const uint32_t*)(Al + rB * EA_STR + kc + ko);
        uint32_t al2 = *(const uint32_t*)(Al + rA * EA_STR + kc + 8 + ko);
        uint32_t al3 = *(const uint32_t*)(Al + rB * EA_STR + kc + 8 + ko);
        uint32_t bh = bh_base + (kc + (lane & 15)) * (EB_STR * 2);
        uint32_t bl = bl_base + (kc + (lane & 15)) * (EB_STR * 2);
#pragma unroll
        for (int t = 0; t < 16; t++) {
            uint32_t b0, b1, c0, c1;
            ldsm2t(b0, b1, bh + t * 16);
            ldsm2t(c0, c1, bl + t * 16);
            mma16816(acc + t * 4, ah0, ah1, ah2, ah3, b0, b1);
            mma16816(acc + t * 4, ah0, ah1, ah2, ah3, c0, c1);
            mma16816(acc + t * 4, al0, al1, al2, al3, b0, b1);
        }
    }
}

// ---------------------------------------------------------------------------
// K4: rel = ht @ seq  (HMMA 3-split)  M=4096 N=1024 K=512, epilogue -> splits
// ---------------------------------------------------------------------------
__global__ __launch_bounds__(256) void gemm_rel_hmma() {
    __nv_bfloat16* As = (__nv_bfloat16*)s_dyn;
    __nv_bfloat16* Bs = (__nv_bfloat16*)s_dyn + 4 * EA_SEG;
    int tid = threadIdx.x, lane = tid & 31, wid = tid >> 5;
    int n0 = blockIdx.x * 128, p0 = blockIdx.y * 128;
    int b = p0 >> 10;
    const __nv_bfloat16* Bh_ = g_seqh + (size_t)b * LQ * HQ;
    const __nv_bfloat16* Bl_ = g_seql + (size_t)b * LQ * HQ;
    // p0 is a global pair row; A rows index g_hth directly (batch-flattened)
    uint4 pfA[4], pfB[4];
    hg_load(pfA, pfB, g_hth, g_htl, LQ, Bh_, Bl_, HQ, p0, n0, 0, tid);
    hg_store(pfA, pfB, As, Bs, 0, tid);
    __syncthreads();

    float acc[64];
#pragma unroll
    for (int t = 0; t < 64; t++) acc[t] = 0.f;
    int rA = wid * 16 + (lane >> 2), rB = rA + 8, ko = (lane & 3) * 2;

    for (int ks = 0; ks < 16; ks++) {
        int st = ks & 1;
        if (ks + 1 < 16)
            hg_load(pfA, pfB, g_hth, g_htl, LQ, Bh_, Bl_, HQ, p0, n0, ks + 1, tid);
        hg_compute(acc, As, Bs, st, rA, rB, ko, lane);
        __syncthreads();
        if (ks + 1 < 16) hg_store(pfA, pfB, As, Bs, st ^ 1, tid);
        __syncthreads();
    }

    int nA = p0 + rA, nB = p0 + rB;
#pragma unroll
    for (int t = 0; t < 16; t++) {
        int col = n0 + t * 8 + (lane & 3) * 2;
        uint32_t hp, lp;
        split2(acc[t * 4 + 0], acc[t * 4 + 1], hp, lp);
        *(uint32_t*)&g_relh[(size_t)nA * HQ + col] = hp;
        *(uint32_t*)&g_rell[(size_t)nA * HQ + col] = lp;
        split2(acc[t * 4 + 2], acc[t * 4 + 3], hp, lp);
        *(uint32_t*)&g_relh[(size_t)nB * HQ + col] = hp;
        *(uint32_t*)&g_rell[(size_t)nB * HQ + col] = lp;
    }
}

// ---------------------------------------------------------------------------
// K5a: entW[z, be, :] = ent_emb[be] @ W_top + bias   (f32x2, tiny)
// ---------------------------------------------------------------------------
__global__ __launch_bounds__(256) void gemm_ent(
    const float* __restrict__ Wh, const float* __restrict__ bh,
    const float* __restrict__ Wt, const float* __restrict__ bt) {
    int z = blockIdx.z;
    int n0 = blockIdx.x * 128;
    int r0 = blockIdx.y * 128;
    const float* W = z ? Wt : Wh;
    const float* bias = z ? bt : bh;

    __shared__ float As[16][128];
    __shared__ float Bsh[16][128];
    int tid = threadIdx.x;
    u64t acc2[8][4];
#pragma unroll
    for (int i = 0; i < 8; i++)
#pragma unroll
        for (int j = 0; j < 4; j++) acc2[i][j] = 0ULL;

    int arow = tid >> 1, akc = (tid & 1) * 8;
    int brow = tid >> 4, bcc = (tid & 15) * 8;
    int rm = (tid >> 4) * 8, rn = (tid & 15) * 8;
    const float* Abase = g_ent_emb + (size_t)r0 * HQ;

    for (int k0 = 0; k0 < HQ; k0 += 16) {
        float4 a0 = *(const float4*)(Abase + (size_t)arow * HQ + k0 + akc);
        float4 a1 = *(const float4*)(Abase + (size_t)arow * HQ + k0 + akc + 4);
        float4 b0 = *(const float4*)(W + (size_t)(k0 + brow) * DQ + n0 + bcc);
        float4 b1 = *(const float4*)(W + (size_t)(k0 + brow) * DQ + n0 + bcc + 4);
        __syncthreads();
        As[akc + 0][arow] = a0.x; As[akc + 1][arow] = a0.y;
        As[akc + 2][arow] = a0.z; As[akc + 3][arow] = a0.w;
        As[akc + 4][arow] = a1.x; As[akc + 5][arow] = a1.y;
        As[akc + 6][arow] = a1.z; As[akc + 7][arow] = a1.w;
        *(float4*)&Bsh[brow][bcc] = b0;
        *(float4*)&Bsh[brow][bcc + 4] = b1;
        __syncthreads();
#pragma unroll
        for (int kk = 0; kk < 16; kk++) {
            float a[8];
            *(float4*)&a[0] = *(const float4*)&As[kk][rm];
            *(float4*)&a[4] = *(const float4*)&As[kk][rm + 4];
            ulonglong2 bu0 = *(const ulonglong2*)&Bsh[kk][rn];
            ulonglong2 bu1 = *(const ulonglong2*)&Bsh[kk][rn + 4];
            u64t b2[4] = {bu0.x, bu0.y, bu1.x, bu1.y};
#pragma unroll
            for (int i = 0; i < 8; i++) {
                u64t a2 = pack2b(a[i]);
#pragma unroll
                for (int j = 0; j < 4; j++) fma2(acc2[i][j], a2, b2[j]);
            }
        }
    }
    float* Cb = g_entW + ((size_t)z * NEQ + r0) * DQ + n0;
#pragma unroll
    for (int i = 0; i < 8; i++)
#pragma unroll
        for (int j = 0; j < 4; j++) {
            float2 v = unpack2(acc2[i][j]);
            int col = rn + 2 * j;
            Cb[(size_t)(rm + i) * DQ + col]     = v.x + bias[n0 + col];
            Cb[(size_t)(rm + i) * DQ + col + 1] = v.y + bias[n0 + col + 1];
        }
}

// ---------------------------------------------------------------------------
// K5b: hv/tv = tanh(rel @ W_bot + gathered entW)  (HMMA 3-split)
// M=4096 N=768 K=1024, z=0/1
// ---------------------------------------------------------------------------
__global__ __launch_bounds__(256) void gemm_extract_hmma(const int* __restrict__ hts) {
    __nv_bfloat16* As = (__nv_bfloat16*)s_dyn;
    __nv_bfloat16* Bs = (__nv_bfloat16*)s_dyn + 4 * EA_SEG;
    int tid = threadIdx.x, lane = tid & 31, wid = tid >> 5;
    int z = blockIdx.z, n0 = blockIdx.x * 128, p0 = blockIdx.y * 128;
    const __nv_bfloat16* Bh_ = g_Wsph + (size_t)z * HQ * DQ;
    const __nv_bfloat16* Bl_ = g_Wspl + (size_t)z * HQ * DQ;

    uint4 pfA[4], pfB[4];
    hg_load(pfA, pfB, g_relh, g_rell, HQ, Bh_, Bl_, DQ, p0, n0, 0, tid);
    hg_store(pfA, pfB, As, Bs, 0, tid);
    __syncthreads();

    float acc[64];
#pragma unroll
    for (int t = 0; t < 64; t++) acc[t] = 0.f;
    int rA = wid * 16 + (lane >> 2), rB = rA + 8, ko = (lane & 3) * 2;

    for (int ks = 0; ks < 32; ks++) {
        int st = ks & 1;
        if (ks + 1 < 32)
            hg_load(pfA, pfB, g_relh, g_rell, HQ, Bh_, Bl_, DQ, p0, n0, ks + 1, tid);
        hg_compute(acc, As, Bs, st, rA, rB, ko, lane);
        __syncthreads();
        if (ks + 1 < 32) hg_store(pfA, pfB, As, Bs, st ^ 1, tid);
        __syncthreads();
    }

    int nA = p0 + rA, nB = p0 + rB;
    int eA = hts[nA * 2 + z], eB = hts[nB * 2 + z];
    const float* ewA = g_entW + ((size_t)z * NEQ + (nA >> 10) * EQ + eA) * DQ + n0;
    const float* ewB = g_entW + ((size_t)z * NEQ + (nB >> 10) * EQ + eB) * DQ + n0;
    float* C = z ? g_tv : g_hv;
#pragma unroll
    for (int t = 0; t < 16; t++) {
        int col = t * 8 + (lane & 3) * 2;
        float2 vA, vB;
        vA.x = tanhf(acc[t * 4 + 0] + ewA[col]);
        vA.y = tanhf(acc[t * 4 + 1] + ewA[col + 1]);
        vB.x = tanhf(acc[t * 4 + 2] + ewB[col]);
        vB.y = tanhf(acc[t * 4 + 3] + ewB[col + 1]);
        *(float2*)&C[(size_t)nA * DQ + n0 + col] = vA;
        *(float2*)&C[(size_t)nB * DQ + n0 + col] = vB;
    }
}

// ---------------------------------------------------------------------------
// K6a: transpose-to-k-major + bf16 hi/lo split of Wb -> g_WbB_h/l [KTOT][128]
// ---------------------------------------------------------------------------
__global__ void k_wbt(const float* __restrict__ Wb) {
    int idx = blockIdx.x * 256 + threadIdx.x;
    if (idx >= KTOT * 128) return;
    int k = idx >> 7;
    int n = idx & 127;
    float w = (n < CQ) ? Wb[(size_t)k * CQ + n] : 0.f;
    __nv_bfloat16 wh = __float2bfloat16(w);
    float r = w - __bfloat162float(wh);
    g_WbB_h[idx] = wh;
    g_WbB_l[idx] = __float2bfloat16(r);
}

// ---------------------------------------------------------------------------
// K6b: final block-bilinear GEMM on HMMA (bf16 3-split, f32 accum).
// ---------------------------------------------------------------------------
#define BSTR 136
#define BTILE (64 * BSTR)

__device__ __forceinline__ void load_pf(uint4* pf, int kb, int i, int tid) {
    size_t kbase = ((size_t)kb * 4096 + (size_t)i * 64) * 128;
#pragma unroll
    for (int q = 0; q < 8; q++) {
        int ch = tid + q * 256;
        int split = ch >> 10;
        int idx = ch & 1023;
        const __nv_bfloat16* src = (split ? g_WbB_l : g_WbB_h) + kbase + (size_t)idx * 8;
        pf[q] = *(const uint4*)src;
    }
}

__device__ __forceinline__ void store_pf(const uint4* pf, __nv_bfloat16* Bbuf,
                                         int st, int tid) {
#pragma unroll
    for (int q = 0; q < 8; q++) {
        int ch = tid + q * 256;
        int split = ch >> 10;
        int idx = ch & 1023;
        int row = idx >> 4, col8 = idx & 15;
        *(uint4*)(Bbuf + (size_t)(st * 2 + split) * BTILE + row * BSTR + col8 * 8) = pf[q];
    }
}

__global__ __launch_bounds__(256, 1) void gemm_final_hmma() {
    float* hv_s = (float*)s_dyn;                          // [128][64]
    __nv_bfloat16* Bbuf = (__nv_bfloat16*)(s_dyn + 32768);
    int tid = threadIdx.x, lane = tid & 31, wid = tid >> 5;
    int p0 = blockIdx.x * 128;
    int kb = blockIdx.y;

    for (int t = tid; t < 128 * 64; t += 256) {
        int r = t >> 6, c = t & 63;
        hv_s[t] = g_hv[(size_t)(p0 + r) * DQ + kb * 64 + c];
    }

    int rA = wid * 16 + (lane >> 2), rB = rA + 8;
    float tvA[16], tvB[16];
    {
        const float* tA = g_tv + (size_t)(p0 + rA) * DQ + kb * 64;
        const float* tB = g_tv + (size_t)(p0 + rB) * DQ + kb * 64;
#pragma unroll
        for (int c = 0; c < 4; c++) {
            int j0 = c * 16 + (lane & 3) * 2;
            tvA[c * 4 + 0] = tA[j0];     tvA[c * 4 + 1] = tA[j0 + 1];
            tvA[c * 4 + 2] = tA[j0 + 8]; tvA[c * 4 + 3] = tA[j0 + 9];
            tvB[c * 4 + 0] = tB[j0];     tvB[c * 4 + 1] = tB[j0 + 1];
            tvB[c * 4 + 2] = tB[j0 + 8]; tvB[c * 4 + 3] = tB[j0 + 9];
        }
    }

    uint4 pf[8];
    load_pf(pf, kb, 0, tid);
    store_pf(pf, Bbuf, 0, tid);
    __syncthreads();

    float acc[64];
#pragma unroll
    for (int t = 0; t < 64; t++) acc[t] = 0.f;

    for (int i = 0; i < 64; i++) {
        int st = i & 1;
        if (i + 1 < 64) load_pf(pf, kb, i + 1, tid);

        float hA = hv_s[rA * 64 + i];
        float hB = hv_s[rB * 64 + i];

#pragma unroll
        for (int c = 0; c < 4; c++) {
            float pA0 = hA * tvA[c * 4 + 0], pA1 = hA * tvA[c * 4 + 1];
            float pA2 = hA * tvA[c * 4 + 2], pA3 = hA * tvA[c * 4 + 3];
            float pB0 = hB * tvB[c * 4 + 0], pB1 = hB * tvB[c * 4 + 1];
            float pB2 = hB * tvB[c * 4 + 2], pB3 = hB * tvB[c * 4 + 3];
            uint32_t ah0 = bfpack(pA0, pA1), ah1 = bfpack(pB0, pB1);
            uint32_t ah2 = bfpack(pA2, pA3), ah3 = bfpack(pB2, pB3);
            float rA0 = pA0 - __bfloat162float(__float2bfloat16(pA0));
            float rA1 = pA1 - __bfloat162float(__float2bfloat16(pA1));
            float rA2 = pA2 - __bfloat162float(__float2bfloat16(pA2));
            float rA3 = pA3 - __bfloat162float(__float2bfloat16(pA3));
            float rB0 = pB0 - __bfloat162float(__float2bfloat16(pB0));
            float rB1 = pB1 - __bfloat162float(__float2bfloat16(pB1));
            float rB2 = pB2 - __bfloat162float(__float2bfloat16(pB2));
            float rB3 = pB3 - __bfloat162float(__float2bfloat16(pB3));
            uint32_t al0 = bfpack(rA0, rA1), al1 = bfpack(rB0, rB1);
            uint32_t al2 = bfpack(rA2, rA3), al3 = bfpack(rB2, rB3);

            int brow = c * 16 + (lane & 15);
            uint32_t base_h = smem_u32(Bbuf + (size_t)(st * 2 + 0) * BTILE + brow * BSTR);
            uint32_t base_l = smem_u32(Bbuf + (size_t)(st * 2 + 1) * BTILE + brow * BSTR);

#pragma unroll
            for (int t = 0; t < 16; t++) {
                uint32_t bh0, bh1, bl0, bl1;
                ldsm2t(bh0, bh1, base_h + t * 16);
                ldsm2t(bl0, bl1, base_l + t * 16);
                mma16816(acc + t * 4, ah0, ah1, ah2, ah3, bh0, bh1);
                mma16816(acc + t * 4, ah0, ah1, ah2, ah3, bl0, bl1);
                mma16816(acc + t * 4, al0, al1, al2, al3, bh0, bh1);
            }
        }
        __syncthreads();
        if (i + 1 < 64) store_pf(pf, Bbuf, st ^ 1, tid);
        __syncthreads();
    }

    float* P = g_part + (size_t)kb * NP * CQ;
#pragma unroll
    for (int t = 0; t < 16; t++) {
        int col = t * 8 + (lane & 3) * 2;
        if (col < CQ) {
            P[(size_t)(p0 + rA) * CQ + col] = acc[t * 4 + 0];
            P[(size_t)(p0 + rB) * CQ + col] = acc[t * 4 + 2];
            if (col + 1 < CQ) {
                P[(size_t)(p0 + rA) * CQ + col + 1] = acc[t * 4 + 1];
                P[(size_t)(p0 + rB) * CQ + col + 1] = acc[t * 4 + 3];
            }
        }
    }
}

// ---------------------------------------------------------------------------
// K7: deterministic split-K reduction + bias
// ---------------------------------------------------------------------------
__global__ void k_reduce(const float* __restrict__ bbias, float* __restrict__ out) {
    int idx = blockIdx.x * 256 + threadIdx.x;
    if (idx < NP * CQ) {
        int c = idx % CQ;
        float s = bbias[c];
#pragma unroll
        for (int z = 0; z < NKB; z++) s += g_part[(size_t)z * NP * CQ + idx];
        out[idx] = s;
    }
}

// ---------------------------------------------------------------------------
extern "C" void kernel_launch(void* const* d_in, const int* in_sizes, int n_in,
                              void* d_out, int out_size) {
    const float* seq     = (const float*)d_in[0];   // [B,L,H]
    const float* ent_lhs = (const float*)d_in[1];   // [B,M,H]
    const float* attn    = (const float*)d_in[2];   // [B,NH,M,L]
    const int*   labels  = (const int*)d_in[3];     // [B,M]
    const int*   hts     = (const int*)d_in[4];     // [B,R,2]
    const float* Wh      = (const float*)d_in[5];   // [2H,D]
    const float* bh      = (const float*)d_in[6];   // [D]
    const float* Wt      = (const float*)d_in[7];
    const float* bt      = (const float*)d_in[8];
    const float* Wb      = (const float*)d_in[9];   // [D*BLK,C]
    const float* bbias   = (const float*)d_in[10];  // [C]
    float* out = (float*)d_out;

    const int FIN_SMEM = 32768 + 4 * BTILE * 2;     // 102400 bytes
    cudaFuncSetAttribute(gemm_final_hmma,
                         cudaFuncAttributeMaxDynamicSharedMemorySize, FIN_SMEM);
    cudaFuncSetAttribute(gemm_rel_hmma,
                         cudaFuncAttributeMaxDynamicSharedMemorySize, HG_SMEM);
    cudaFuncSetAttribute(gemm_extract_hmma,
                         cudaFuncAttributeMaxDynamicSharedMemorySize, HG_SMEM);

    k_build<<<BQ, EQ>>>(labels);
    k_ent_emb<<<NEQ, 256>>>(ent_lhs);
    k_ent_attn<<<dim3(NHQ, NEQ), 128>>>(attn);
    k_ht<<<NP, 128>>>(hts);
    k_seqsplit<<<(BQ * LQ * HQ + 255) / 256, 256>>>(seq);
    k_wsplit<<<(2 * HQ * DQ + 255) / 256, 256>>>(Wh, Wt);
    k_wbt<<<(KTOT * 128 + 255) / 256, 256>>>(Wb);
    gemm_rel_hmma<<<dim3(HQ / 128, NP / 128), 256, HG_SMEM>>>();
    gemm_ent<<<dim3(DQ / 128, NEQ / 128, 2), 256>>>(Wh, bh, Wt, bt);
    gemm_extract_hmma<<<dim3(DQ / 128, NP / 128, 2), 256, HG_SMEM>>>(hts);
    gemm_final_hmma<<<dim3(NP / 128, NKB), 256, FIN_SMEM>>>();
    k_reduce<<<(NP * CQ + 255) / 256, 256>>>(bbias, out);
}

// round 15
// speedup vs baseline: 1.0017x; 1.0017x over previous
#include <cuda_runtime.h>
#include <cuda_bf16.h>
#include <math.h>
#include <stdint.h>

// Problem constants
#define BQ 4
#define LQ 512
#define HQ 1024
#define MQ 128
#define EQ 64
#define NHQ 16
#define RQ 1024
#define DQ 768
#define BLKQ 64
#define CQ 97
#define NKB 12           // D / BLK  (split-K planes)
#define NP (BQ * RQ)     // 4096 pairs
#define NEQ (BQ * EQ)    // 256 distinct entities
#define KTOT 49152       // D * BLK

// -------- scratch (static device globals: allocation-guard safe) ----------
__device__ float g_ent_emb[NEQ * HQ];              // 1 MB
__device__ int   g_cnt[NEQ];
__device__ int   g_list[NEQ * MQ];
__device__ float g_ent_attn[NEQ * NHQ * LQ];       // 8 MB
__device__ __nv_bfloat16 g_hth[NP * LQ];           // 4 MB  ht hi split
__device__ __nv_bfloat16 g_htl[NP * LQ];           // 4 MB  ht lo split
__device__ __nv_bfloat16 g_seqh[BQ * LQ * HQ];     // 4 MB  seq hi
__device__ __nv_bfloat16 g_seql[BQ * LQ * HQ];     // 4 MB  seq lo
__device__ __nv_bfloat16 g_relh[NP * HQ];          // 8 MB  rel hi
__device__ __nv_bfloat16 g_rell[NP * HQ];          // 8 MB  rel lo
__device__ __nv_bfloat16 g_Wsph[2 * HQ * DQ];      // 3 MB  W bottom-half hi (z-major)
__device__ __nv_bfloat16 g_Wspl[2 * HQ * DQ];      // 3 MB  W bottom-half lo
__device__ float g_hv[NP * DQ];                    // 12 MB
__device__ float g_tv[NP * DQ];                    // 12 MB
__device__ float g_entW[2 * NEQ * DQ];             // 1.5 MB
__device__ float g_part[NKB * NP * CQ];            // 19 MB split-K partials
__device__ __nv_bfloat16 g_WbB_h[KTOT * 128];      // 12.6 MB  Wb k-major hi
__device__ __nv_bfloat16 g_WbB_l[KTOT * 128];      // 12.6 MB  Wb k-major lo

// -------- packed f32x2 helpers (used by gemm_ent) ----
typedef unsigned long long u64t;

__device__ __forceinline__ u64t pack2b(float v) {
    u64t r; asm("mov.b64 %0, {%1, %1};" : "=l"(r) : "f"(v)); return r;
}
__device__ __forceinline__ void fma2(u64t& d, u64t a, u64t b) {
    asm("fma.rn.f32x2 %0, %1, %2, %0;" : "+l"(d) : "l"(a), "l"(b));
}
__device__ __forceinline__ float2 unpack2(u64t v) {
    float2 r; asm("mov.b64 {%0, %1}, %2;" : "=f"(r.x), "=f"(r.y) : "l"(v)); return r;
}

// -------- HMMA helpers ----
__device__ __forceinline__ uint32_t smem_u32(const void* p) {
    return (uint32_t)__cvta_generic_to_shared(p);
}
__device__ __forceinline__ void mma16816(float* d, uint32_t a0, uint32_t a1,
                                         uint32_t a2, uint32_t a3,
                                         uint32_t b0, uint32_t b1) {
    asm volatile(
        "mma.sync.aligned.m16n8k16.row.col.f32.bf16.bf16.f32 "
        "{%0,%1,%2,%3}, {%4,%5,%6,%7}, {%8,%9}, {%0,%1,%2,%3};"
        : "+f"(d[0]), "+f"(d[1]), "+f"(d[2]), "+f"(d[3])
        : "r"(a0), "r"(a1), "r"(a2), "r"(a3), "r"(b0), "r"(b1));
}
__device__ __forceinline__ void ldsm2t(uint32_t& r0, uint32_t& r1, uint32_t addr) {
    asm volatile("ldmatrix.sync.aligned.m8n8.x2.trans.shared.b16 {%0,%1}, [%2];"
                 : "=r"(r0), "=r"(r1) : "r"(addr));
}
__device__ __forceinline__ uint32_t bfpack(float lo, float hi) {
    __nv_bfloat162 t = __floats2bfloat162_rn(lo, hi);
    return *(uint32_t*)&t;
}
__device__ __forceinline__ void split2(float a0, float a1, uint32_t& hp, uint32_t& lp) {
    __nv_bfloat16 h0 = __float2bfloat16(a0), h1 = __float2bfloat16(a1);
    hp = (uint32_t)__bfloat16_as_ushort(h0) | ((uint32_t)__bfloat16_as_ushort(h1) << 16);
    lp = bfpack(a0 - __bfloat162float(h0), a1 - __bfloat162float(h1));
}

extern __shared__ char s_dyn[];

// ---------------------------------------------------------------------------
// K0: per (b,e) mention index lists
// ---------------------------------------------------------------------------
__global__ void k_build(const int* __restrict__ labels) {
    int b = blockIdx.x, e = threadIdx.x;
    int c = 0;
    int* lst = g_list + (b * EQ + e) * MQ;
    for (int m = 0; m < MQ; m++)
        if (labels[b * MQ + m] == e) lst[c++] = m;
    g_cnt[b * EQ + e] = c;
}

// ---------------------------------------------------------------------------
// K1: segment logsumexp over mentions -> ent_emb [B,E,H]
// ---------------------------------------------------------------------------
__global__ void k_ent_emb(const float* __restrict__ ent_lhs) {
    int be = blockIdx.x;
    int b = be / EQ;
    __shared__ int s_list[MQ];
    int cnt = g_cnt[be];
    for (int i = threadIdx.x; i < cnt; i += 256) s_list[i] = g_list[be * MQ + i];
    __syncthreads();
    const float* base = ent_lhs + (size_t)b * MQ * HQ;
    for (int h = threadIdx.x; h < HQ; h += 256) {
        float o = 0.f;
        if (cnt > 0) {
            float mx = -3.4e38f;
            for (int i = 0; i < cnt; i++) mx = fmaxf(mx, base[s_list[i] * HQ + h]);
            float s = 0.f;
            for (int i = 0; i < cnt; i++) s += expf(base[s_list[i] * HQ + h] - mx);
            o = mx + logf(s);
        }
        g_ent_emb[be * HQ + h] = o;
    }
}

// ---------------------------------------------------------------------------
// K2: mean mention attention -> ent_attn [B,E,NH,L]
// ---------------------------------------------------------------------------
__global__ void k_ent_attn(const float* __restrict__ attn) {
    int be = blockIdx.y, nh = blockIdx.x;
    int b = be / EQ;
    int cnt = g_cnt[be];
    __shared__ int s_list[MQ];
    for (int i = threadIdx.x; i < cnt; i += 128) s_list[i] = g_list[be * MQ + i];
    __syncthreads();
    float inv = (cnt > 0) ? 1.f / (float)cnt : 0.f;
    const float* abase = attn + ((size_t)(b * NHQ + nh)) * MQ * LQ;
    float* obase = g_ent_attn + ((size_t)(be * NHQ + nh)) * LQ;
    for (int l = threadIdx.x; l < LQ; l += 128) {
        float s = 0.f;
        for (int i = 0; i < cnt; i++) s += abase[s_list[i] * LQ + l];
        obase[l] = s * inv;
    }
}

// ---------------------------------------------------------------------------
// K3: pair attention product, mean over heads, normalize -> bf16 splits
// ---------------------------------------------------------------------------
__global__ void k_ht(const int* __restrict__ hts) {
    int n = blockIdx.x;
    int b = n / RQ;
    int he = hts[n * 2 + 0];
    int te = hts[n * 2 + 1];
    const float* ha = g_ent_attn + ((size_t)(b * EQ + he)) * NHQ * LQ;
    const float* ta = g_ent_attn + ((size_t)(b * EQ + te)) * NHQ * LQ;
    float v[4];
    float loc = 0.f;
#pragma unroll
    for (int rep = 0; rep < 4; rep++) {
        int l = threadIdx.x + rep * 128;
        float acc = 0.f;
#pragma unroll
        for (int nh = 0; nh < NHQ; nh++) acc += ha[nh * LQ + l] * ta[nh * LQ + l];
        v[rep] = acc * (1.0f / NHQ);
        loc += v[rep];
    }
    __shared__ float red[128];
    red[threadIdx.x] = loc;
    __syncthreads();
    for (int s = 64; s > 0; s >>= 1) {
        if (threadIdx.x < s) red[threadIdx.x] += red[threadIdx.x + s];
        __syncthreads();
    }
    float inv = 1.f / (red[0] + 1e-5f);
#pragma unroll
    for (int rep = 0; rep < 4; rep++) {
        int l = threadIdx.x + rep * 128;
        float val = v[rep] * inv;
        __nv_bfloat16 h = __float2bfloat16(val);
        g_hth[(size_t)n * LQ + l] = h;
        g_htl[(size_t)n * LQ + l] = __float2bfloat16(val - __bfloat162float(h));
    }
}

// ---------------------------------------------------------------------------
// K3b/K3c: bf16 hi/lo splits of seq and W bottom halves
// ---------------------------------------------------------------------------
__global__ void k_seqsplit(const float* __restrict__ seq) {
    int idx = blockIdx.x * 256 + threadIdx.x;
    if (idx >= BQ * LQ * HQ) return;
    float w = seq[idx];
    __nv_bfloat16 h = __float2bfloat16(w);
    g_seqh[idx] = h;
    g_seql[idx] = __float2bfloat16(w - __bfloat162float(h));
}

__global__ void k_wsplit(const float* __restrict__ Wh, const float* __restrict__ Wt) {
    int idx = blockIdx.x * 256 + threadIdx.x;
    if (idx >= 2 * HQ * DQ) return;
    int z = idx / (HQ * DQ);
    int r = idx - z * (HQ * DQ);
    float w = (z ? Wt : Wh)[(size_t)(HQ + r / DQ) * DQ + (r % DQ)];
    __nv_bfloat16 h = __float2bfloat16(w);
    g_Wsph[idx] = h;
    g_Wspl[idx] = __float2bfloat16(w - __bfloat162float(h));
}

// ---------------------------------------------------------------------------
// HMMA GEMM tiles: A [128 rows][32 k] pad-40 bf16 hi/lo, B [32 k][128 n]
// pad-136 bf16 hi/lo, double buffered. 8 warps, each 16 rows x 128 cols.
// ---------------------------------------------------------------------------
#define EA_STR 40
#define EB_STR 136
#define EA_SEG (128 * EA_STR)            // 5120 elems
#define EB_SEG (32 * EB_STR)             // 4352 elems
#define HG_SMEM ((4 * EA_SEG + 4 * EB_SEG) * 2)   // 75776 bytes

__device__ __forceinline__ void hg_load(uint4* pfA, uint4* pfB,
        const __nv_bfloat16* Ah_, const __nv_bfloat16* Al_, int astr,
        const __nv_bfloat16* Bh_, const __nv_bfloat16* Bl_, int bstr,
        int p0, int n0, int ks, int tid) {
#pragma unroll
    for (int q = 0; q < 4; q++) {
        int ch = tid + q * 256;          // 0..1023
        int sp = ch >> 9, idx = ch & 511;
        {
            int row = idx >> 2, c8 = idx & 3;
            const __nv_bfloat16* src = (sp ? Al_ : Ah_) +
                (size_t)(p0 + row) * astr + ks * 32 + c8 * 8;
            pfA[q] = *(const uint4*)src;
        }
        {
            int kr = idx >> 4, c8 = idx & 15;
            const __nv_bfloat16* src = (sp ? Bl_ : Bh_) +
                (size_t)(ks * 32 + kr) * bstr + n0 + c8 * 8;
            pfB[q] = *(const uint4*)src;
        }
    }
}

__device__ __forceinline__ void hg_store(const uint4* pfA, const uint4* pfB,
        __nv_bfloat16* As, __nv_bfloat16* Bs, int st, int tid) {
#pragma unroll
    for (int q = 0; q < 4; q++) {
        int ch = tid + q * 256;
        int sp = ch >> 9, idx = ch & 511;
        {
            int row = idx >> 2, c8 = idx & 3;
            *(uint4*)(As + (st * 2 + sp) * EA_SEG + row * EA_STR + c8 * 8) = pfA[q];
        }
        {
            int kr = idx >> 4, c8 = idx & 15;
            *(uint4*)(Bs + (st * 2 + sp) * EB_SEG + kr * EB_STR + c8 * 8) = pfB[q];
        }
    }
}

__device__ __forceinline__ void hg_compute(float* acc, const __nv_bfloat16* As,
        __nv_bfloat16* Bs, int st, int rA, int rB, int ko, int lane) {
    const __nv_bfloat16* Ah = As + (st * 2 + 0) * EA_SEG;
    const __nv_bfloat16* Al = As + (st * 2 + 1) * EA_SEG;
    uint32_t bh_base = smem_u32(Bs + (st * 2 + 0) * EB_SEG);
    uint32_t bl_base = smem_u32(Bs + (st * 2 + 1) * EB_SEG);
#pragma unroll
    for (int kc = 0; kc < 32; kc += 16) {
        uint32_t ah0 = *(const uint32_t*)(Ah + rA * EA_STR + kc + ko);
        uint32_t ah1 = *(const uint32_t*)(Ah + rB * EA_STR + kc + ko);
        uint32_t ah2 = *(const uint32_t*)(Ah + rA * EA_STR + kc + 8 + ko);
        uint32_t ah3 = *(const uint32_t*)(Ah + rB * EA_STR + kc + 8 + ko);
        uint32_t al0 = *(const uint32_t*)(Al + rA * EA_STR + kc + ko);
        uint32_t al1 = *(const uint32_t*)(Al + rB * EA_STR + kc + ko);
        uint32_t al2 = *(const uint32_t*)(Al + rA * EA_STR + kc + 8 + ko);
        uint32_t al3 = *(const uint32_t*)(Al + rB * EA_STR + kc + 8 + ko);
        uint32_t bh = bh_base + (kc + (lane & 15)) * (EB_STR * 2);
        uint32_t bl = bl_base + (kc + (lane & 15)) * (EB_STR * 2);
#pragma unroll
        for (int t = 0; t < 16; t++) {
            uint32_t b0, b1, c0, c1;
            ldsm2t(b0, b1, bh + t * 16);
            ldsm2t(c0, c1, bl + t * 16);
            mma16816(acc + t * 4, ah0, ah1, ah2, ah3, b0, b1);
            mma16816(acc + t * 4, ah0, ah1, ah2, ah3, c0, c1);
            mma16816(acc + t * 4, al0, al1, al2, al3, b0, b1);
        }
    }
}

// ---------------------------------------------------------------------------
// K4: rel = ht @ seq  (HMMA 3-split)  M=4096 N=1024 K=512, epilogue -> splits
// ---------------------------------------------------------------------------
__global__ __launch_bounds__(256) void gemm_rel_hmma() {
    __nv_bfloat16* As = (__nv_bfloat16*)s_dyn;
    __nv_bfloat16* Bs = (__nv_bfloat16*)s_dyn + 4 * EA_SEG;
    int tid = threadIdx.x, lane = tid & 31, wid = tid >> 5;
    int n0 = blockIdx.x * 128, p0 = blockIdx.y * 128;
    int b = p0 >> 10;
    const __nv_bfloat16* Bh_ = g_seqh + (size_t)b * LQ * HQ;
    const __nv_bfloat16* Bl_ = g_seql + (size_t)b * LQ * HQ;
    // p0 is a global pair row; A rows index g_hth directly (batch-flattened)
    uint4 pfA[4], pfB[4];
    hg_load(pfA, pfB, g_hth, g_htl, LQ, Bh_, Bl_, HQ, p0, n0, 0, tid);
    hg_store(pfA, pfB, As, Bs, 0, tid);
    __syncthreads();

    float acc[64];
#pragma unroll
    for (int t = 0; t < 64; t++) acc[t] = 0.f;
    int rA = wid * 16 + (lane >> 2), rB = rA + 8, ko = (lane & 3) * 2;

    for (int ks = 0; ks < 16; ks++) {
        int st = ks & 1;
        if (ks + 1 < 16)
            hg_load(pfA, pfB, g_hth, g_htl, LQ, Bh_, Bl_, HQ, p0, n0, ks + 1, tid);
        hg_compute(acc, As, Bs, st, rA, rB, ko, lane);
        __syncthreads();
        if (ks + 1 < 16) hg_store(pfA, pfB, As, Bs, st ^ 1, tid);
        __syncthreads();
    }

    int nA = p0 + rA, nB = p0 + rB;
#pragma unroll
    for (int t = 0; t < 16; t++) {
        int col = n0 + t * 8 + (lane & 3) * 2;
        uint32_t hp, lp;
        split2(acc[t * 4 + 0], acc[t * 4 + 1], hp, lp);
        *(uint32_t*)&g_relh[(size_t)nA * HQ + col] = hp;
        *(uint32_t*)&g_rell[(size_t)nA * HQ + col] = lp;
        split2(acc[t * 4 + 2], acc[t * 4 + 3], hp, lp);
        *(uint32_t*)&g_relh[(size_t)nB * HQ + col] = hp;
        *(uint32_t*)&g_rell[(size_t)nB * HQ + col] = lp;
    }
}

// ---------------------------------------------------------------------------
// K5a: entW[z, be, :] = ent_emb[be] @ W_top + bias   (f32x2, tiny)
// ---------------------------------------------------------------------------
__global__ __launch_bounds__(256) void gemm_ent(
    const float* __restrict__ Wh, const float* __restrict__ bh,
    const float* __restrict__ Wt, const float* __restrict__ bt) {
    int z = blockIdx.z;
    int n0 = blockIdx.x * 128;
    int r0 = blockIdx.y * 128;
    const float* W = z ? Wt : Wh;
    const float* bias = z ? bt : bh;

    __shared__ float As[16][128];
    __shared__ float Bsh[16][128];
    int tid = threadIdx.x;
    u64t acc2[8][4];
#pragma unroll
    for (int i = 0; i < 8; i++)
#pragma unroll
        for (int j = 0; j < 4; j++) acc2[i][j] = 0ULL;

    int arow = tid >> 1, akc = (tid & 1) * 8;
    int brow = tid >> 4, bcc = (tid & 15) * 8;
    int rm = (tid >> 4) * 8, rn = (tid & 15) * 8;
    const float* Abase = g_ent_emb + (size_t)r0 * HQ;

    for (int k0 = 0; k0 < HQ; k0 += 16) {
        float4 a0 = *(const float4*)(Abase + (size_t)arow * HQ + k0 + akc);
        float4 a1 = *(const float4*)(Abase + (size_t)arow * HQ + k0 + akc + 4);
        float4 b0 = *(const float4*)(W + (size_t)(k0 + brow) * DQ + n0 + bcc);
        float4 b1 = *(const float4*)(W + (size_t)(k0 + brow) * DQ + n0 + bcc + 4);
        __syncthreads();
        As[akc + 0][arow] = a0.x; As[akc + 1][arow] = a0.y;
        As[akc + 2][arow] = a0.z; As[akc + 3][arow] = a0.w;
        As[akc + 4][arow] = a1.x; As[akc + 5][arow] = a1.y;
        As[akc + 6][arow] = a1.z; As[akc + 7][arow] = a1.w;
        *(float4*)&Bsh[brow][bcc] = b0;
        *(float4*)&Bsh[brow][bcc + 4] = b1;
        __syncthreads();
#pragma unroll
        for (int kk = 0; kk < 16; kk++) {
            float a[8];
            *(float4*)&a[0] = *(const float4*)&As[kk][rm];
            *(float4*)&a[4] = *(const float4*)&As[kk][rm + 4];
            ulonglong2 bu0 = *(const ulonglong2*)&Bsh[kk][rn];
            ulonglong2 bu1 = *(const ulonglong2*)&Bsh[kk][rn + 4];
            u64t b2[4] = {bu0.x, bu0.y, bu1.x, bu1.y};
#pragma unroll
            for (int i = 0; i < 8; i++) {
                u64t a2 = pack2b(a[i]);
#pragma unroll
                for (int j = 0; j < 4; j++) fma2(acc2[i][j], a2, b2[j]);
            }
        }
    }
    float* Cb = g_entW + ((size_t)z * NEQ + r0) * DQ + n0;
#pragma unroll
    for (int i = 0; i < 8; i++)
#pragma unroll
        for (int j = 0; j < 4; j++) {
            float2 v = unpack2(acc2[i][j]);
            int col = rn + 2 * j;
            Cb[(size_t)(rm + i) * DQ + col]     = v.x + bias[n0 + col];
            Cb[(size_t)(rm + i) * DQ + col + 1] = v.y + bias[n0 + col + 1];
        }
}

// ---------------------------------------------------------------------------
// K5b: hv/tv = tanh(rel @ W_bot + gathered entW)  (HMMA 3-split)
// M=4096 N=768 K=1024, z=0/1
// ---------------------------------------------------------------------------
__global__ __launch_bounds__(256) void gemm_extract_hmma(const int* __restrict__ hts) {
    __nv_bfloat16* As = (__nv_bfloat16*)s_dyn;
    __nv_bfloat16* Bs = (__nv_bfloat16*)s_dyn + 4 * EA_SEG;
    int tid = threadIdx.x, lane = tid & 31, wid = tid >> 5;
    int z = blockIdx.z, n0 = blockIdx.x * 128, p0 = blockIdx.y * 128;
    const __nv_bfloat16* Bh_ = g_Wsph + (size_t)z * HQ * DQ;
    const __nv_bfloat16* Bl_ = g_Wspl + (size_t)z * HQ * DQ;

    uint4 pfA[4], pfB[4];
    hg_load(pfA, pfB, g_relh, g_rell, HQ, Bh_, Bl_, DQ, p0, n0, 0, tid);
    hg_store(pfA, pfB, As, Bs, 0, tid);
    __syncthreads();

    float acc[64];
#pragma unroll
    for (int t = 0; t < 64; t++) acc[t] = 0.f;
    int rA = wid * 16 + (lane >> 2), rB = rA + 8, ko = (lane & 3) * 2;

    for (int ks = 0; ks < 32; ks++) {
        int st = ks & 1;
        if (ks + 1 < 32)
            hg_load(pfA, pfB, g_relh, g_rell, HQ, Bh_, Bl_, DQ, p0, n0, ks + 1, tid);
        hg_compute(acc, As, Bs, st, rA, rB, ko, lane);
        __syncthreads();
        if (ks + 1 < 32) hg_store(pfA, pfB, As, Bs, st ^ 1, tid);
        __syncthreads();
    }

    int nA = p0 + rA, nB = p0 + rB;
    int eA = hts[nA * 2 + z], eB = hts[nB * 2 + z];
    const float* ewA = g_entW + ((size_t)z * NEQ + (nA >> 10) * EQ + eA) * DQ + n0;
    const float* ewB = g_entW + ((size_t)z * NEQ + (nB >> 10) * EQ + eB) * DQ + n0;
    float* C = z ? g_tv : g_hv;
#pragma unroll
    for (int t = 0; t < 16; t++) {
        int col = t * 8 + (lane & 3) * 2;
        float2 vA, vB;
        vA.x = tanhf(acc[t * 4 + 0] + ewA[col]);
        vA.y = tanhf(acc[t * 4 + 1] + ewA[col + 1]);
        vB.x = tanhf(acc[t * 4 + 2] + ewB[col]);
        vB.y = tanhf(acc[t * 4 + 3] + ewB[col + 1]);
        *(float2*)&C[(size_t)nA * DQ + n0 + col] = vA;
        *(float2*)&C[(size_t)nB * DQ + n0 + col] = vB;
    }
}

// ---------------------------------------------------------------------------
// K6a: transpose-to-k-major + bf16 hi/lo split of Wb -> g_WbB_h/l [KTOT][128]
// ---------------------------------------------------------------------------
__global__ void k_wbt(const float* __restrict__ Wb) {
    int idx = blockIdx.x * 256 + threadIdx.x;
    if (idx >= KTOT * 128) return;
    int k = idx >> 7;
    int n = idx & 127;
    float w = (n < CQ) ? Wb[(size_t)k * CQ + n] : 0.f;
    __nv_bfloat16 wh = __float2bfloat16(w);
    float r = w - __bfloat162float(wh);
    g_WbB_h[idx] = wh;
    g_WbB_l[idx] = __float2bfloat16(r);
}

// ---------------------------------------------------------------------------
// K6b: final block-bilinear GEMM on HMMA (bf16 3-split, f32 accum).
// ---------------------------------------------------------------------------
#define BSTR 136
#define BTILE (64 * BSTR)

__device__ __forceinline__ void load_pf(uint4* pf, int kb, int i, int tid) {
    size_t kbase = ((size_t)kb * 4096 + (size_t)i * 64) * 128;
#pragma unroll
    for (int q = 0; q < 8; q++) {
        int ch = tid + q * 256;
        int split = ch >> 10;
        int idx = ch & 1023;
        const __nv_bfloat16* src = (split ? g_WbB_l : g_WbB_h) + kbase + (size_t)idx * 8;
        pf[q] = *(const uint4*)src;
    }
}

__device__ __forceinline__ void store_pf(const uint4* pf, __nv_bfloat16* Bbuf,
                                         int st, int tid) {
#pragma unroll
    for (int q = 0; q < 8; q++) {
        int ch = tid + q * 256;
        int split = ch >> 10;
        int idx = ch & 1023;
        int row = idx >> 4, col8 = idx & 15;
        *(uint4*)(Bbuf + (size_t)(st * 2 + split) * BTILE + row * BSTR + col8 * 8) = pf[q];
    }
}

__global__ __launch_bounds__(256, 1) void gemm_final_hmma() {
    float* hv_s = (float*)s_dyn;                          // [128][64]
    __nv_bfloat16* Bbuf = (__nv_bfloat16*)(s_dyn + 32768);
    int tid = threadIdx.x, lane = tid & 31, wid = tid >> 5;
    int p0 = blockIdx.x * 128;
    int kb = blockIdx.y;

    for (int t = tid; t < 128 * 64; t += 256) {
        int r = t >> 6, c = t & 63;
        hv_s[t] = g_hv[(size_t)(p0 + r) * DQ + kb * 64 + c];
    }

    int rA = wid * 16 + (lane >> 2), rB = rA + 8;
    float tvA[16], tvB[16];
    {
        const float* tA = g_tv + (size_t)(p0 + rA) * DQ + kb * 64;
        const float* tB = g_tv + (size_t)(p0 + rB) * DQ + kb * 64;
#pragma unroll
        for (int c = 0; c < 4; c++) {
            int j0 = c * 16 + (lane & 3) * 2;
            tvA[c * 4 + 0] = tA[j0];     tvA[c * 4 + 1] = tA[j0 + 1];
            tvA[c * 4 + 2] = tA[j0 + 8]; tvA[c * 4 + 3] = tA[j0 + 9];
            tvB[c * 4 + 0] = tB[j0];     tvB[c * 4 + 1] = tB[j0 + 1];
            tvB[c * 4 + 2] = tB[j0 + 8]; tvB[c * 4 + 3] = tB[j0 + 9];
        }
    }

    uint4 pf[8];
    load_pf(pf, kb, 0, tid);
    store_pf(pf, Bbuf, 0, tid);
    __syncthreads();

    float acc[64];
#pragma unroll
    for (int t = 0; t < 64; t++) acc[t] = 0.f;

    for (int i = 0; i < 64; i++) {
        int st = i & 1;
        if (i + 1 < 64) load_pf(pf, kb, i + 1, tid);

        float hA = hv_s[rA * 64 + i];
        float hB = hv_s[rB * 64 + i];

#pragma unroll
        for (int c = 0; c < 4; c++) {
            float pA0 = hA * tvA[c * 4 + 0], pA1 = hA * tvA[c * 4 + 1];
            float pA2 = hA * tvA[c * 4 + 2], pA3 = hA * tvA[c * 4 + 3];
            float pB0 = hB * tvB[c * 4 + 0], pB1 = hB * tvB[c * 4 + 1];
            float pB2 = hB * tvB[c * 4 + 2], pB3 = hB * tvB[c * 4 + 3];
            uint32_t ah0 = bfpack(pA0, pA1), ah1 = bfpack(pB0, pB1);
            uint32_t ah2 = bfpack(pA2, pA3), ah3 = bfpack(pB2, pB3);
            float rA0 = pA0 - __bfloat162float(__float2bfloat16(pA0));
            float rA1 = pA1 - __bfloat162float(__float2bfloat16(pA1));
            float rA2 = pA2 - __bfloat162float(__float2bfloat16(pA2));
            float rA3 = pA3 - __bfloat162float(__float2bfloat16(pA3));
            float rB0 = pB0 - __bfloat162float(__float2bfloat16(pB0));
            float rB1 = pB1 - __bfloat162float(__float2bfloat16(pB1));
            float rB2 = pB2 - __bfloat162float(__float2bfloat16(pB2));
            float rB3 = pB3 - __bfloat162float(__float2bfloat16(pB3));
            uint32_t al0 = bfpack(rA0, rA1), al1 = bfpack(rB0, rB1);
            uint32_t al2 = bfpack(rA2, rA3), al3 = bfpack(rB2, rB3);

            int brow = c * 16 + (lane & 15);
            uint32_t base_h = smem_u32(Bbuf + (size_t)(st * 2 + 0) * BTILE + brow * BSTR);
            uint32_t base_l = smem_u32(Bbuf + (size_t)(st * 2 + 1) * BTILE + brow * BSTR);

#pragma unroll
            for (int t = 0; t < 16; t++) {
                uint32_t bh0, bh1, bl0, bl1;
                ldsm2t(bh0, bh1, base_h + t * 16);
                ldsm2t(bl0, bl1, base_l + t * 16);
                mma16816(acc + t * 4, ah0, ah1, ah2, ah3, bh0, bh1);
                mma16816(acc + t * 4, ah0, ah1, ah2, ah3, bl0, bl1);
                mma16816(acc + t * 4, al0, al1, al2, al3, bh0, bh1);
            }
        }
        __syncthreads();
        if (i + 1 < 64) store_pf(pf, Bbuf, st ^ 1, tid);
        __syncthreads();
    }

    float* P = g_part + (size_t)kb * NP * CQ;
#pragma unroll
    for (int t = 0; t < 16; t++) {
        int col = t * 8 + (lane & 3) * 2;
        if (col < CQ) {
            P[(size_t)(p0 + rA) * CQ + col] = acc[t * 4 + 0];
            P[(size_t)(p0 + rB) * CQ + col] = acc[t * 4 + 2];
            if (col + 1 < CQ) {
                P[(size_t)(p0 + rA) * CQ + col + 1] = acc[t * 4 + 1];
                P[(size_t)(p0 + rB) * CQ + col + 1] = acc[t * 4 + 3];
            }
        }
    }
}

// ---------------------------------------------------------------------------
// K7: deterministic split-K reduction + bias
// ---------------------------------------------------------------------------
__global__ void k_reduce(const float* __restrict__ bbias, float* __restrict__ out) {
    int idx = blockIdx.x * 256 + threadIdx.x;
    if (idx < NP * CQ) {
        int c = idx % CQ;
        float s = bbias[c];
#pragma unroll
        for (int z = 0; z < NKB; z++) s += g_part[(size_t)z * NP * CQ + idx];
        out[idx] = s;
    }
}

// ---------------------------------------------------------------------------
extern "C" void kernel_launch(void* const* d_in, const int* in_sizes, int n_in,
                              void* d_out, int out_size) {
    const float* seq     = (const float*)d_in[0];   // [B,L,H]
    const float* ent_lhs = (const float*)d_in[1];   // [B,M,H]
    const float* attn    = (const float*)d_in[2];   // [B,NH,M,L]
    const int*   labels  = (const int*)d_in[3];     // [B,M]
    const int*   hts     = (const int*)d_in[4];     // [B,R,2]
    const float* Wh      = (const float*)d_in[5];   // [2H,D]
    const float* bh      = (const float*)d_in[6];   // [D]
    const float* Wt      = (const float*)d_in[7];
    const float* bt      = (const float*)d_in[8];
    const float* Wb      = (const float*)d_in[9];   // [D*BLK,C]
    const float* bbias   = (const float*)d_in[10];  // [C]
    float* out = (float*)d_out;

    const int FIN_SMEM = 32768 + 4 * BTILE * 2;     // 102400 bytes
    cudaFuncSetAttribute(gemm_final_hmma,
                         cudaFuncAttributeMaxDynamicSharedMemorySize, FIN_SMEM);
    cudaFuncSetAttribute(gemm_rel_hmma,
                         cudaFuncAttributeMaxDynamicSharedMemorySize, HG_SMEM);
    cudaFuncSetAttribute(gemm_extract_hmma,
                         cudaFuncAttributeMaxDynamicSharedMemorySize, HG_SMEM);

    k_build<<<BQ, EQ>>>(labels);
    k_ent_emb<<<NEQ, 256>>>(ent_lhs);
    k_ent_attn<<<dim3(NHQ, NEQ), 128>>>(attn);
    k_ht<<<NP, 128>>>(hts);
    k_seqsplit<<<(BQ * LQ * HQ + 255) / 256, 256>>>(seq);
    k_wsplit<<<(2 * HQ * DQ + 255) / 256, 256>>>(Wh, Wt);
    k_wbt<<<(KTOT * 128 + 255) / 256, 256>>>(Wb);
    gemm_rel_hmma<<<dim3(HQ / 128, NP / 128), 256, HG_SMEM>>>();
    gemm_ent<<<dim3(DQ / 128, NEQ / 128, 2), 256>>>(Wh, bh, Wt, bt);
    gemm_extract_hmma<<<dim3(DQ / 128, NP / 128, 2), 256, HG_SMEM>>>(hts);
    gemm_final_hmma<<<dim3(NP / 128, NKB), 256, FIN_SMEM>>>();
    k_reduce<<<(NP * CQ + 255) / 256, 256>>>(bbias, out);
}

// round 16
// speedup vs baseline: 1.0020x; 1.0003x over previous
#include <cuda_runtime.h>
#include <cuda_bf16.h>
#include <math.h>
#include <stdint.h>

// Problem constants
#define BQ 4
#define LQ 512
#define HQ 1024
#define MQ 128
#define EQ 64
#define NHQ 16
#define RQ 1024
#define DQ 768
#define BLKQ 64
#define CQ 97
#define NKB 12           // D / BLK  (split-K planes)
#define NP (BQ * RQ)     // 4096 pairs
#define NEQ (BQ * EQ)    // 256 distinct entities
#define KTOT 49152       // D * BLK

// -------- scratch (static device globals: allocation-guard safe) ----------
__device__ float g_ent_emb[NEQ * HQ];              // 1 MB
__device__ int   g_cnt[NEQ];
__device__ int   g_list[NEQ * MQ];
__device__ float g_ent_attn[NEQ * NHQ * LQ];       // 8 MB
__device__ __nv_bfloat16 g_hth[NP * LQ];           // 4 MB  ht hi split
__device__ __nv_bfloat16 g_htl[NP * LQ];           // 4 MB  ht lo split
__device__ __nv_bfloat16 g_seqh[BQ * LQ * HQ];     // 4 MB  seq hi
__device__ __nv_bfloat16 g_seql[BQ * LQ * HQ];     // 4 MB  seq lo
__device__ __nv_bfloat16 g_relh[NP * HQ];          // 8 MB  rel hi
__device__ __nv_bfloat16 g_rell[NP * HQ];          // 8 MB  rel lo
__device__ __nv_bfloat16 g_Wsph[2 * HQ * DQ];      // 3 MB  W bottom-half hi (z-major)
__device__ __nv_bfloat16 g_Wspl[2 * HQ * DQ];      // 3 MB  W bottom-half lo
__device__ float g_hv[NP * DQ];                    // 12 MB
__device__ float g_tv[NP * DQ];                    // 12 MB
__device__ float g_entW[2 * NEQ * DQ];             // 1.5 MB
__device__ float g_part[NKB * NP * CQ];            // 19 MB split-K partials
__device__ __nv_bfloat16 g_WbB_h[KTOT * 128];      // 12.6 MB  Wb k-major hi
__device__ __nv_bfloat16 g_WbB_l[KTOT * 128];      // 12.6 MB  Wb k-major lo

// -------- packed f32x2 helpers (used by gemm_ent) ----
typedef unsigned long long u64t;

__device__ __forceinline__ u64t pack2b(float v) {
    u64t r; asm("mov.b64 %0, {%1, %1};" : "=l"(r) : "f"(v)); return r;
}
__device__ __forceinline__ void fma2(u64t& d, u64t a, u64t b) {
    asm("fma.rn.f32x2 %0, %1, %2, %0;" : "+l"(d) : "l"(a), "l"(b));
}
__device__ __forceinline__ float2 unpack2(u64t v) {
    float2 r; asm("mov.b64 {%0, %1}, %2;" : "=f"(r.x), "=f"(r.y) : "l"(v)); return r;
}

// -------- HMMA helpers ----
__device__ __forceinline__ uint32_t smem_u32(const void* p) {
    return (uint32_t)__cvta_generic_to_shared(p);
}
__device__ __forceinline__ void mma16816(float* d, uint32_t a0, uint32_t a1,
                                         uint32_t a2, uint32_t a3,
                                         uint32_t b0, uint32_t b1) {
    asm volatile(
        "mma.sync.aligned.m16n8k16.row.col.f32.bf16.bf16.f32 "
        "{%0,%1,%2,%3}, {%4,%5,%6,%7}, {%8,%9}, {%0,%1,%2,%3};"
        : "+f"(d[0]), "+f"(d[1]), "+f"(d[2]), "+f"(d[3])
        : "r"(a0), "r"(a1), "r"(a2), "r"(a3), "r"(b0), "r"(b1));
}
__device__ __forceinline__ void ldsm2t(uint32_t& r0, uint32_t& r1, uint32_t addr) {
    asm volatile("ldmatrix.sync.aligned.m8n8.x2.trans.shared.b16 {%0,%1}, [%2];"
                 : "=r"(r0), "=r"(r1) : "r"(addr));
}
__device__ __forceinline__ uint32_t bfpack(float lo, float hi) {
    __nv_bfloat162 t = __floats2bfloat162_rn(lo, hi);
    return *(uint32_t*)&t;
}
__device__ __forceinline__ void split2(float a0, float a1, uint32_t& hp, uint32_t& lp) {
    __nv_bfloat16 h0 = __float2bfloat16(a0), h1 = __float2bfloat16(a1);
    hp = (uint32_t)__bfloat16_as_ushort(h0) | ((uint32_t)__bfloat16_as_ushort(h1) << 16);
    lp = bfpack(a0 - __bfloat162float(h0), a1 - __bfloat162float(h1));
}

extern __shared__ char s_dyn[];

// ---------------------------------------------------------------------------
// K0: per (b,e) mention index lists
// ---------------------------------------------------------------------------
__global__ void k_build(const int* __restrict__ labels) {
    int b = blockIdx.x, e = threadIdx.x;
    int c = 0;
    int* lst = g_list + (b * EQ + e) * MQ;
    for (int m = 0; m < MQ; m++)
        if (labels[b * MQ + m] == e) lst[c++] = m;
    g_cnt[b * EQ + e] = c;
}

// ---------------------------------------------------------------------------
// K1: segment logsumexp over mentions -> ent_emb [B,E,H]
// ---------------------------------------------------------------------------
__global__ void k_ent_emb(const float* __restrict__ ent_lhs) {
    int be = blockIdx.x;
    int b = be / EQ;
    __shared__ int s_list[MQ];
    int cnt = g_cnt[be];
    for (int i = threadIdx.x; i < cnt; i += 256) s_list[i] = g_list[be * MQ + i];
    __syncthreads();
    const float* base = ent_lhs + (size_t)b * MQ * HQ;
    for (int h = threadIdx.x; h < HQ; h += 256) {
        float o = 0.f;
        if (cnt > 0) {
            float mx = -3.4e38f;
            for (int i = 0; i < cnt; i++) mx = fmaxf(mx, base[s_list[i] * HQ + h]);
            float s = 0.f;
            for (int i = 0; i < cnt; i++) s += expf(base[s_list[i] * HQ + h] - mx);
            o = mx + logf(s);
        }
        g_ent_emb[be * HQ + h] = o;
    }
}

// ---------------------------------------------------------------------------
// K2: mean mention attention -> ent_attn [B,E,NH,L]
// ---------------------------------------------------------------------------
__global__ void k_ent_attn(const float* __restrict__ attn) {
    int be = blockIdx.y, nh = blockIdx.x;
    int b = be / EQ;
    int cnt = g_cnt[be];
    __shared__ int s_list[MQ];
    for (int i = threadIdx.x; i < cnt; i += 128) s_list[i] = g_list[be * MQ + i];
    __syncthreads();
    float inv = (cnt > 0) ? 1.f / (float)cnt : 0.f;
    const float* abase = attn + ((size_t)(b * NHQ + nh)) * MQ * LQ;
    float* obase = g_ent_attn + ((size_t)(be * NHQ + nh)) * LQ;
    for (int l = threadIdx.x; l < LQ; l += 128) {
        float s = 0.f;
        for (int i = 0; i < cnt; i++) s += abase[s_list[i] * LQ + l];
        obase[l] = s * inv;
    }
}

// ---------------------------------------------------------------------------
// K3: pair attention product, mean over heads, normalize -> bf16 splits
// ---------------------------------------------------------------------------
__global__ void k_ht(const int* __restrict__ hts) {
    int n = blockIdx.x;
    int b = n / RQ;
    int he = hts[n * 2 + 0];
    int te = hts[n * 2 + 1];
    const float* ha = g_ent_attn + ((size_t)(b * EQ + he)) * NHQ * LQ;
    const float* ta = g_ent_attn + ((size_t)(b * EQ + te)) * NHQ * LQ;
    float v[4];
    float loc = 0.f;
#pragma unroll
    for (int rep = 0; rep < 4; rep++) {
        int l = threadIdx.x + rep * 128;
        float acc = 0.f;
#pragma unroll
        for (int nh = 0; nh < NHQ; nh++) acc += ha[nh * LQ + l] * ta[nh * LQ + l];
        v[rep] = acc * (1.0f / NHQ);
        loc += v[rep];
    }
    __shared__ float red[128];
    red[threadIdx.x] = loc;
    __syncthreads();
    for (int s = 64; s > 0; s >>= 1) {
        if (threadIdx.x < s) red[threadIdx.x] += red[threadIdx.x + s];
        __syncthreads();
    }
    float inv = 1.f / (red[0] + 1e-5f);
#pragma unroll
    for (int rep = 0; rep < 4; rep++) {
        int l = threadIdx.x + rep * 128;
        float val = v[rep] * inv;
        __nv_bfloat16 h = __float2bfloat16(val);
        g_hth[(size_t)n * LQ + l] = h;
        g_htl[(size_t)n * LQ + l] = __float2bfloat16(val - __bfloat162float(h));
    }
}

// ---------------------------------------------------------------------------
// K3b/K3c: bf16 hi/lo splits of seq and W bottom halves
// ---------------------------------------------------------------------------
__global__ void k_seqsplit(const float* __restrict__ seq) {
    int idx = blockIdx.x * 256 + threadIdx.x;
    if (idx >= BQ * LQ * HQ) return;
    float w = seq[idx];
    __nv_bfloat16 h = __float2bfloat16(w);
    g_seqh[idx] = h;
    g_seql[idx] = __float2bfloat16(w - __bfloat162float(h));
}

__global__ void k_wsplit(const float* __restrict__ Wh, const float* __restrict__ Wt) {
    int idx = blockIdx.x * 256 + threadIdx.x;
    if (idx >= 2 * HQ * DQ) return;
    int z = idx / (HQ * DQ);
    int r = idx - z * (HQ * DQ);
    float w = (z ? Wt : Wh)[(size_t)(HQ + r / DQ) * DQ + (r % DQ)];
    __nv_bfloat16 h = __float2bfloat16(w);
    g_Wsph[idx] = h;
    g_Wspl[idx] = __float2bfloat16(w - __bfloat162float(h));
}

// ---------------------------------------------------------------------------
// HMMA GEMM tiles: A [128 rows][32 k] pad-40 bf16 hi/lo, B [32 k][128 n]
// pad-136 bf16 hi/lo, double buffered. 8 warps, each 16 rows x 128 cols.
// ---------------------------------------------------------------------------
#define EA_STR 40
#define EB_STR 136
#define EA_SEG (128 * EA_STR)            // 5120 elems
#define EB_SEG (32 * EB_STR)             // 4352 elems
#define HG_SMEM ((4 * EA_SEG + 4 * EB_SEG) * 2)   // 75776 bytes

__device__ __forceinline__ void hg_load(uint4* pfA, uint4* pfB,
        const __nv_bfloat16* Ah_, const __nv_bfloat16* Al_, int astr,
        const __nv_bfloat16* Bh_, const __nv_bfloat16* Bl_, int bstr,
        int p0, int n0, int ks, int tid) {
#pragma unroll
    for (int q = 0; q < 4; q++) {
        int ch = tid + q * 256;          // 0..1023
        int sp = ch >> 9, idx = ch & 511;
        {
            int row = idx >> 2, c8 = idx & 3;
            const __nv_bfloat16* src = (sp ? Al_ : Ah_) +
                (size_t)(p0 + row) * astr + ks * 32 + c8 * 8;
            pfA[q] = *(const uint4*)src;
        }
        {
            int kr = idx >> 4, c8 = idx & 15;
            const __nv_bfloat16* src = (sp ? Bl_ : Bh_) +
                (size_t)(ks * 32 + kr) * bstr + n0 + c8 * 8;
            pfB[q] = *(const uint4*)src;
        }
    }
}

__device__ __forceinline__ void hg_store(const uint4* pfA, const uint4* pfB,
        __nv_bfloat16* As, __nv_bfloat16* Bs, int st, int tid) {
#pragma unroll
    for (int q = 0; q < 4; q++) {
        int ch = tid + q * 256;
        int sp = ch >> 9, idx = ch & 511;
        {
            int row = idx >> 2, c8 = idx & 3;
            *(uint4*)(As + (st * 2 + sp) * EA_SEG + row * EA_STR + c8 * 8) = pfA[q];
        }
        {
            int kr = idx >> 4, c8 = idx & 15;
            *(uint4*)(Bs + (st * 2 + sp) * EB_SEG + kr * EB_STR + c8 * 8) = pfB[q];
        }
    }
}

__device__ __forceinline__ void hg_compute(float* acc, const __nv_bfloat16* As,
        __nv_bfloat16* Bs, int st, int rA, int rB, int ko, int lane) {
    const __nv_bfloat16* Ah = As + (st * 2 + 0) * EA_SEG;
    const __nv_bfloat16* Al = As + (st * 2 + 1) * EA_SEG;
    uint32_t bh_base = smem_u32(Bs + (st * 2 + 0) * EB_SEG);
    uint32_t bl_base = smem_u32(Bs + (st * 2 + 1) * EB_SEG);
#pragma unroll
    for (int kc = 0; kc < 32; kc += 16) {
        uint32_t ah0 = *(const uint32_t*)(Ah + rA * EA_STR + kc + ko);
        uint32_t ah1 = *(const uint32_t*)(Ah + rB * EA_STR + kc + ko);
        uint32_t ah2 = *(const uint32_t*)(Ah + rA * EA_STR + kc + 8 + ko);
        uint32_t ah3 = *(const uint32_t*)(Ah + rB * EA_STR + kc + 8 + ko);
        uint32_t al0 = *(const uint32_t*)(Al + rA * EA_STR + kc + ko);
        uint32_t al1 = *(const uint32_t*)(Al + rB * EA_STR + kc + ko);
        uint32_t al2 = *(const uint32_t*)(Al + rA * EA_STR + kc + 8 + ko);
        uint32_t al3 = *(const uint32_t*)(Al + rB * EA_STR + kc + 8 + ko);
        uint32_t bh = bh_base + (kc + (lane & 15)) * (EB_STR * 2);
        uint32_t bl = bl_base + (kc + (lane & 15)) * (EB_STR * 2);
#pragma unroll
        for (int t = 0; t < 16; t++) {
            uint32_t b0, b1, c0, c1;
            ldsm2t(b0, b1, bh + t * 16);
            ldsm2t(c0, c1, bl + t * 16);
            mma16816(acc + t * 4, ah0, ah1, ah2, ah3, b0, b1);
            mma16816(acc + t * 4, ah0, ah1, ah2, ah3, c0, c1);
            mma16816(acc + t * 4, al0, al1, al2, al3, b0, b1);
        }
    }
}

// ---------------------------------------------------------------------------
// K4: rel = ht @ seq  (HMMA 3-split)  M=4096 N=1024 K=512, epilogue -> splits
// ---------------------------------------------------------------------------
__global__ __launch_bounds__(256) void gemm_rel_hmma() {
    __nv_bfloat16* As = (__nv_bfloat16*)s_dyn;
    __nv_bfloat16* Bs = (__nv_bfloat16*)s_dyn + 4 * EA_SEG;
    int tid = threadIdx.x, lane = tid & 31, wid = tid >> 5;
    int n0 = blockIdx.x * 128, p0 = blockIdx.y * 128;
    int b = p0 >> 10;
    const __nv_bfloat16* Bh_ = g_seqh + (size_t)b * LQ * HQ;
    const __nv_bfloat16* Bl_ = g_seql + (size_t)b * LQ * HQ;
    // p0 is a global pair row; A rows index g_hth directly (batch-flattened)
    uint4 pfA[4], pfB[4];
    hg_load(pfA, pfB, g_hth, g_htl, LQ, Bh_, Bl_, HQ, p0, n0, 0, tid);
    hg_store(pfA, pfB, As, Bs, 0, tid);
    __syncthreads();

    float acc[64];
#pragma unroll
    for (int t = 0; t < 64; t++) acc[t] = 0.f;
    int rA = wid * 16 + (lane >> 2), rB = rA + 8, ko = (lane & 3) * 2;

    for (int ks = 0; ks < 16; ks++) {
        int st = ks & 1;
        if (ks + 1 < 16)
            hg_load(pfA, pfB, g_hth, g_htl, LQ, Bh_, Bl_, HQ, p0, n0, ks + 1, tid);
        hg_compute(acc, As, Bs, st, rA, rB, ko, lane);
        __syncthreads();
        if (ks + 1 < 16) hg_store(pfA, pfB, As, Bs, st ^ 1, tid);
        __syncthreads();
    }

    int nA = p0 + rA, nB = p0 + rB;
#pragma unroll
    for (int t = 0; t < 16; t++) {
        int col = n0 + t * 8 + (lane & 3) * 2;
        uint32_t hp, lp;
        split2(acc[t * 4 + 0], acc[t * 4 + 1], hp, lp);
        *(uint32_t*)&g_relh[(size_t)nA * HQ + col] = hp;
        *(uint32_t*)&g_rell[(size_t)nA * HQ + col] = lp;
        split2(acc[t * 4 + 2], acc[t * 4 + 3], hp, lp);
        *(uint32_t*)&g_relh[(size_t)nB * HQ + col] = hp;
        *(uint32_t*)&g_rell[(size_t)nB * HQ + col] = lp;
    }
}

// ---------------------------------------------------------------------------
// K5a: entW[z, be, :] = ent_emb[be] @ W_top + bias   (f32x2, tiny)
// ---------------------------------------------------------------------------
__global__ __launch_bounds__(256) void gemm_ent(
    const float* __restrict__ Wh, const float* __restrict__ bh,
    const float* __restrict__ Wt, const float* __restrict__ bt) {
    int z = blockIdx.z;
    int n0 = blockIdx.x * 128;
    int r0 = blockIdx.y * 128;
    const float* W = z ? Wt : Wh;
    const float* bias = z ? bt : bh;

    __shared__ float As[16][128];
    __shared__ float Bsh[16][128];
    int tid = threadIdx.x;
    u64t acc2[8][4];
#pragma unroll
    for (int i = 0; i < 8; i++)
#pragma unroll
        for (int j = 0; j < 4; j++) acc2[i][j] = 0ULL;

    int arow = tid >> 1, akc = (tid & 1) * 8;
    int brow = tid >> 4, bcc = (tid & 15) * 8;
    int rm = (tid >> 4) * 8, rn = (tid & 15) * 8;
    const float* Abase = g_ent_emb + (size_t)r0 * HQ;

    for (int k0 = 0; k0 < HQ; k0 += 16) {
        float4 a0 = *(const float4*)(Abase + (size_t)arow * HQ + k0 + akc);
        float4 a1 = *(const float4*)(Abase + (size_t)arow * HQ + k0 + akc + 4);
        float4 b0 = *(const float4*)(W + (size_t)(k0 + brow) * DQ + n0 + bcc);
        float4 b1 = *(const float4*)(W + (size_t)(k0 + brow) * DQ + n0 + bcc + 4);
        __syncthreads();
        As[akc + 0][arow] = a0.x; As[akc + 1][arow] = a0.y;
        As[akc + 2][arow] = a0.z; As[akc + 3][arow] = a0.w;
        As[akc + 4][arow] = a1.x; As[akc + 5][arow] = a1.y;
        As[akc + 6][arow] = a1.z; As[akc + 7][arow] = a1.w;
        *(float4*)&Bsh[brow][bcc] = b0;
        *(float4*)&Bsh[brow][bcc + 4] = b1;
        __syncthreads();
#pragma unroll
        for (int kk = 0; kk < 16; kk++) {
            float a[8];
            *(float4*)&a[0] = *(const float4*)&As[kk][rm];
            *(float4*)&a[4] = *(const float4*)&As[kk][rm + 4];
            ulonglong2 bu0 = *(const ulonglong2*)&Bsh[kk][rn];
            ulonglong2 bu1 = *(const ulonglong2*)&Bsh[kk][rn + 4];
            u64t b2[4] = {bu0.x, bu0.y, bu1.x, bu1.y};
#pragma unroll
            for (int i = 0; i < 8; i++) {
                u64t a2 = pack2b(a[i]);
#pragma unroll
                for (int j = 0; j < 4; j++) fma2(acc2[i][j], a2, b2[j]);
            }
        }
    }
    float* Cb = g_entW + ((size_t)z * NEQ + r0) * DQ + n0;
#pragma unroll
    for (int i = 0; i < 8; i++)
#pragma unroll
        for (int j = 0; j < 4; j++) {
            float2 v = unpack2(acc2[i][j]);
            int col = rn + 2 * j;
            Cb[(size_t)(rm + i) * DQ + col]     = v.x + bias[n0 + col];
            Cb[(size_t)(rm + i) * DQ + col + 1] = v.y + bias[n0 + col + 1];
        }
}

// ---------------------------------------------------------------------------
// K5b: hv/tv = tanh(rel @ W_bot + gathered entW)  (HMMA 3-split)
// M=4096 N=768 K=1024, z=0/1
// ---------------------------------------------------------------------------
__global__ __launch_bounds__(256) void gemm_extract_hmma(const int* __restrict__ hts) {
    __nv_bfloat16* As = (__nv_bfloat16*)s_dyn;
    __nv_bfloat16* Bs = (__nv_bfloat16*)s_dyn + 4 * EA_SEG;
    int tid = threadIdx.x, lane = tid & 31, wid = tid >> 5;
    int z = blockIdx.z, n0 = blockIdx.x * 128, p0 = blockIdx.y * 128;
    const __nv_bfloat16* Bh_ = g_Wsph + (size_t)z * HQ * DQ;
    const __nv_bfloat16* Bl_ = g_Wspl + (size_t)z * HQ * DQ;

    uint4 pfA[4], pfB[4];
    hg_load(pfA, pfB, g_relh, g_rell, HQ, Bh_, Bl_, DQ, p0, n0, 0, tid);
    hg_store(pfA, pfB, As, Bs, 0, tid);
    __syncthreads();

    float acc[64];
#pragma unroll
    for (int t = 0; t < 64; t++) acc[t] = 0.f;
    int rA = wid * 16 + (lane >> 2), rB = rA + 8, ko = (lane & 3) * 2;

    for (int ks = 0; ks < 32; ks++) {
        int st = ks & 1;
        if (ks + 1 < 32)
            hg_load(pfA, pfB, g_relh, g_rell, HQ, Bh_, Bl_, DQ, p0, n0, ks + 1, tid);
        hg_compute(acc, As, Bs, st, rA, rB, ko, lane);
        __syncthreads();
        if (ks + 1 < 32) hg_store(pfA, pfB, As, Bs, st ^ 1, tid);
        __syncthreads();
    }

    int nA = p0 + rA, nB = p0 + rB;
    int eA = hts[nA * 2 + z], eB = hts[nB * 2 + z];
    const float* ewA = g_entW + ((size_t)z * NEQ + (nA >> 10) * EQ + eA) * DQ + n0;
    const float* ewB = g_entW + ((size_t)z * NEQ + (nB >> 10) * EQ + eB) * DQ + n0;
    float* C = z ? g_tv : g_hv;
#pragma unroll
    for (int t = 0; t < 16; t++) {
        int col = t * 8 + (lane & 3) * 2;
        float2 vA, vB;
        vA.x = tanhf(acc[t * 4 + 0] + ewA[col]);
        vA.y = tanhf(acc[t * 4 + 1] + ewA[col + 1]);
        vB.x = tanhf(acc[t * 4 + 2] + ewB[col]);
        vB.y = tanhf(acc[t * 4 + 3] + ewB[col + 1]);
        *(float2*)&C[(size_t)nA * DQ + n0 + col] = vA;
        *(float2*)&C[(size_t)nB * DQ + n0 + col] = vB;
    }
}

// ---------------------------------------------------------------------------
// K6a: transpose-to-k-major + bf16 hi/lo split of Wb -> g_WbB_h/l [KTOT][128]
// ---------------------------------------------------------------------------
__global__ void k_wbt(const float* __restrict__ Wb) {
    int idx = blockIdx.x * 256 + threadIdx.x;
    if (idx >= KTOT * 128) return;
    int k = idx >> 7;
    int n = idx & 127;
    float w = (n < CQ) ? Wb[(size_t)k * CQ + n] : 0.f;
    __nv_bfloat16 wh = __float2bfloat16(w);
    float r = w - __bfloat162float(wh);
    g_WbB_h[idx] = wh;
    g_WbB_l[idx] = __float2bfloat16(r);
}

// ---------------------------------------------------------------------------
// K6b: final block-bilinear GEMM on HMMA (bf16 3-split, f32 accum).
// ---------------------------------------------------------------------------
#define BSTR 136
#define BTILE (64 * BSTR)

__device__ __forceinline__ void load_pf(uint4* pf, int kb, int i, int tid) {
    size_t kbase = ((size_t)kb * 4096 + (size_t)i * 64) * 128;
#pragma unroll
    for (int q = 0; q < 8; q++) {
        int ch = tid + q * 256;
        int split = ch >> 10;
        int idx = ch & 1023;
        const __nv_bfloat16* src = (split ? g_WbB_l : g_WbB_h) + kbase + (size_t)idx * 8;
        pf[q] = *(const uint4*)src;
    }
}

__device__ __forceinline__ void store_pf(const uint4* pf, __nv_bfloat16* Bbuf,
                                         int st, int tid) {
#pragma unroll
    for (int q = 0; q < 8; q++) {
        int ch = tid + q * 256;
        int split = ch >> 10;
        int idx = ch & 1023;
        int row = idx >> 4, col8 = idx & 15;
        *(uint4*)(Bbuf + (size_t)(st * 2 + split) * BTILE + row * BSTR + col8 * 8) = pf[q];
    }
}

__global__ __launch_bounds__(256, 1) void gemm_final_hmma() {
    float* hv_s = (float*)s_dyn;                          // [128][64]
    __nv_bfloat16* Bbuf = (__nv_bfloat16*)(s_dyn + 32768);
    int tid = threadIdx.x, lane = tid & 31, wid = tid >> 5;
    int p0 = blockIdx.x * 128;
    int kb = blockIdx.y;

    for (int t = tid; t < 128 * 64; t += 256) {
        int r = t >> 6, c = t & 63;
        hv_s[t] = g_hv[(size_t)(p0 + r) * DQ + kb * 64 + c];
    }

    int rA = wid * 16 + (lane >> 2), rB = rA + 8;
    float tvA[16], tvB[16];
    {
        const float* tA = g_tv + (size_t)(p0 + rA) * DQ + kb * 64;
        const float* tB = g_tv + (size_t)(p0 + rB) * DQ + kb * 64;
#pragma unroll
        for (int c = 0; c < 4; c++) {
            int j0 = c * 16 + (lane & 3) * 2;
            tvA[c * 4 + 0] = tA[j0];     tvA[c * 4 + 1] = tA[j0 + 1];
            tvA[c * 4 + 2] = tA[j0 + 8]; tvA[c * 4 + 3] = tA[j0 + 9];
            tvB[c * 4 + 0] = tB[j0];     tvB[c * 4 + 1] = tB[j0 + 1];
            tvB[c * 4 + 2] = tB[j0 + 8]; tvB[c * 4 + 3] = tB[j0 + 9];
        }
    }

    uint4 pf[8];
    load_pf(pf, kb, 0, tid);
    store_pf(pf, Bbuf, 0, tid);
    __syncthreads();

    float acc[64];
#pragma unroll
    for (int t = 0; t < 64; t++) acc[t] = 0.f;

    for (int i = 0; i < 64; i++) {
        int st = i & 1;
        if (i + 1 < 64) load_pf(pf, kb, i + 1, tid);

        float hA = hv_s[rA * 64 + i];
        float hB = hv_s[rB * 64 + i];

#pragma unroll
        for (int c = 0; c < 4; c++) {
            float pA0 = hA * tvA[c * 4 + 0], pA1 = hA * tvA[c * 4 + 1];
            float pA2 = hA * tvA[c * 4 + 2], pA3 = hA * tvA[c * 4 + 3];
            float pB0 = hB * tvB[c * 4 + 0], pB1 = hB * tvB[c * 4 + 1];
            float pB2 = hB * tvB[c * 4 + 2], pB3 = hB * tvB[c * 4 + 3];
            uint32_t ah0 = bfpack(pA0, pA1), ah1 = bfpack(pB0, pB1);
            uint32_t ah2 = bfpack(pA2, pA3), ah3 = bfpack(pB2, pB3);
            float rA0 = pA0 - __bfloat162float(__float2bfloat16(pA0));
            float rA1 = pA1 - __bfloat162float(__float2bfloat16(pA1));
            float rA2 = pA2 - __bfloat162float(__float2bfloat16(pA2));
            float rA3 = pA3 - __bfloat162float(__float2bfloat16(pA3));
            float rB0 = pB0 - __bfloat162float(__float2bfloat16(pB0));
            float rB1 = pB1 - __bfloat162float(__float2bfloat16(pB1));
            float rB2 = pB2 - __bfloat162float(__float2bfloat16(pB2));
            float rB3 = pB3 - __bfloat162float(__float2bfloat16(pB3));
            uint32_t al0 = bfpack(rA0, rA1), al1 = bfpack(rB0, rB1);
            uint32_t al2 = bfpack(rA2, rA3), al3 = bfpack(rB2, rB3);

            int brow = c * 16 + (lane & 15);
            uint32_t base_h = smem_u32(Bbuf + (size_t)(st * 2 + 0) * BTILE + brow * BSTR);
            uint32_t base_l = smem_u32(Bbuf + (size_t)(st * 2 + 1) * BTILE + brow * BSTR);

#pragma unroll
            for (int t = 0; t < 16; t++) {
                uint32_t bh0, bh1, bl0, bl1;
                ldsm2t(bh0, bh1, base_h + t * 16);
                ldsm2t(bl0, bl1, base_l + t * 16);
                mma16816(acc + t * 4, ah0, ah1, ah2, ah3, bh0, bh1);
                mma16816(acc + t * 4, ah0, ah1, ah2, ah3, bl0, bl1);
                mma16816(acc + t * 4, al0, al1, al2, al3, bh0, bh1);
            }
        }
        __syncthreads();
        if (i + 1 < 64) store_pf(pf, Bbuf, st ^ 1, tid);
        __syncthreads();
    }

    float* P = g_part + (size_t)kb * NP * CQ;
#pragma unroll
    for (int t = 0; t < 16; t++) {
        int col = t * 8 + (lane & 3) * 2;
        if (col < CQ) {
            P[(size_t)(p0 + rA) * CQ + col] = acc[t * 4 + 0];
            P[(size_t)(p0 + rB) * CQ + col] = acc[t * 4 + 2];
            if (col + 1 < CQ) {
                P[(size_t)(p0 + rA) * CQ + col + 1] = acc[t * 4 + 1];
                P[(size_t)(p0 + rB) * CQ + col + 1] = acc[t * 4 + 3];
            }
        }
    }
}

// ---------------------------------------------------------------------------
// K7: deterministic split-K reduction + bias
// ---------------------------------------------------------------------------
__global__ void k_reduce(const float* __restrict__ bbias, float* __restrict__ out) {
    int idx = blockIdx.x * 256 + threadIdx.x;
    if (idx < NP * CQ) {
        int c = idx % CQ;
        float s = bbias[c];
#pragma unroll
        for (int z = 0; z < NKB; z++) s += g_part[(size_t)z * NP * CQ + idx];
        out[idx] = s;
    }
}

// ---------------------------------------------------------------------------
extern "C" void kernel_launch(void* const* d_in, const int* in_sizes, int n_in,
                              void* d_out, int out_size) {
    const float* seq     = (const float*)d_in[0];   // [B,L,H]
    const float* ent_lhs = (const float*)d_in[1];   // [B,M,H]
    const float* attn    = (const float*)d_in[2];   // [B,NH,M,L]
    const int*   labels  = (const int*)d_in[3];     // [B,M]
    const int*   hts     = (const int*)d_in[4];     // [B,R,2]
    const float* Wh      = (const float*)d_in[5];   // [2H,D]
    const float* bh      = (const float*)d_in[6];   // [D]
    const float* Wt      = (const float*)d_in[7];
    const float* bt      = (const float*)d_in[8];
    const float* Wb      = (const float*)d_in[9];   // [D*BLK,C]
    const float* bbias   = (const float*)d_in[10];  // [C]
    float* out = (float*)d_out;

    const int FIN_SMEM = 32768 + 4 * BTILE * 2;     // 102400 bytes
    cudaFuncSetAttribute(gemm_final_hmma,
                         cudaFuncAttributeMaxDynamicSharedMemorySize, FIN_SMEM);
    cudaFuncSetAttribute(gemm_rel_hmma,
                         cudaFuncAttributeMaxDynamicSharedMemorySize, HG_SMEM);
    cudaFuncSetAttribute(gemm_extract_hmma,
                         cudaFuncAttributeMaxDynamicSharedMemorySize, HG_SMEM);

    k_build<<<BQ, EQ>>>(labels);
    k_ent_emb<<<NEQ, 256>>>(ent_lhs);
    k_ent_attn<<<dim3(NHQ, NEQ), 128>>>(attn);
    k_ht<<<NP, 128>>>(hts);
    k_seqsplit<<<(BQ * LQ * HQ + 255) / 256, 256>>>(seq);
    k_wsplit<<<(2 * HQ * DQ + 255) / 256, 256>>>(Wh, Wt);
    k_wbt<<<(KTOT * 128 + 255) / 256, 256>>>(Wb);
    gemm_rel_hmma<<<dim3(HQ / 128, NP / 128), 256, HG_SMEM>>>();
    gemm_ent<<<dim3(DQ / 128, NEQ / 128, 2), 256>>>(Wh, bh, Wt, bt);
    gemm_extract_hmma<<<dim3(DQ / 128, NP / 128, 2), 256, HG_SMEM>>>(hts);
    gemm_final_hmma<<<dim3(NP / 128, NKB), 256, FIN_SMEM>>>();
    k_reduce<<<(NP * CQ + 255) / 256, 256>>>(bbias, out);
}

// round 17
// speedup vs baseline: 1.0026x; 1.0006x over previous
#include <cuda_runtime.h>
#include <cuda_bf16.h>
#include <math.h>
#include <stdint.h>

// Problem constants
#define BQ 4
#define LQ 512
#define HQ 1024
#define MQ 128
#define EQ 64
#define NHQ 16
#define RQ 1024
#define DQ 768
#define BLKQ 64
#define CQ 97
#define NKB 12           // D / BLK  (split-K planes)
#define NP (BQ * RQ)     // 4096 pairs
#define NEQ (BQ * EQ)    // 256 distinct entities
#define KTOT 49152       // D * BLK

// -------- scratch (static device globals: allocation-guard safe) ----------
__device__ float g_ent_emb[NEQ * HQ];              // 1 MB
__device__ int   g_cnt[NEQ];
__device__ int   g_list[NEQ * MQ];
__device__ float g_ent_attn[NEQ * NHQ * LQ];       // 8 MB
__device__ __nv_bfloat16 g_hth[NP * LQ];           // 4 MB  ht hi split
__device__ __nv_bfloat16 g_htl[NP * LQ];           // 4 MB  ht lo split
__device__ __nv_bfloat16 g_seqh[BQ * LQ * HQ];     // 4 MB  seq hi
__device__ __nv_bfloat16 g_seql[BQ * LQ * HQ];     // 4 MB  seq lo
__device__ __nv_bfloat16 g_relh[NP * HQ];          // 8 MB  rel hi
__device__ __nv_bfloat16 g_rell[NP * HQ];          // 8 MB  rel lo
__device__ __nv_bfloat16 g_Wsph[2 * HQ * DQ];      // 3 MB  W bottom-half hi (z-major)
__device__ __nv_bfloat16 g_Wspl[2 * HQ * DQ];      // 3 MB  W bottom-half lo
__device__ float g_hv[NP * DQ];                    // 12 MB
__device__ float g_tv[NP * DQ];                    // 12 MB
__device__ float g_entW[2 * NEQ * DQ];             // 1.5 MB
__device__ float g_part[NKB * NP * CQ];            // 19 MB split-K partials
__device__ __nv_bfloat16 g_WbB_h[KTOT * 128];      // 12.6 MB  Wb k-major hi
__device__ __nv_bfloat16 g_WbB_l[KTOT * 128];      // 12.6 MB  Wb k-major lo

// -------- packed f32x2 helpers (used by gemm_ent) ----
typedef unsigned long long u64t;

__device__ __forceinline__ u64t pack2b(float v) {
    u64t r; asm("mov.b64 %0, {%1, %1};" : "=l"(r) : "f"(v)); return r;
}
__device__ __forceinline__ void fma2(u64t& d, u64t a, u64t b) {
    asm("fma.rn.f32x2 %0, %1, %2, %0;" : "+l"(d) : "l"(a), "l"(b));
}
__device__ __forceinline__ float2 unpack2(u64t v) {
    float2 r; asm("mov.b64 {%0, %1}, %2;" : "=f"(r.x), "=f"(r.y) : "l"(v)); return r;
}

// -------- HMMA helpers ----
__device__ __forceinline__ uint32_t smem_u32(const void* p) {
    return (uint32_t)__cvta_generic_to_shared(p);
}
__device__ __forceinline__ void mma16816(float* d, uint32_t a0, uint32_t a1,
                                         uint32_t a2, uint32_t a3,
                                         uint32_t b0, uint32_t b1) {
    asm volatile(
        "mma.sync.aligned.m16n8k16.row.col.f32.bf16.bf16.f32 "
        "{%0,%1,%2,%3}, {%4,%5,%6,%7}, {%8,%9}, {%0,%1,%2,%3};"
        : "+f"(d[0]), "+f"(d[1]), "+f"(d[2]), "+f"(d[3])
        : "r"(a0), "r"(a1), "r"(a2), "r"(a3), "r"(b0), "r"(b1));
}
__device__ __forceinline__ void ldsm2t(uint32_t& r0, uint32_t& r1, uint32_t addr) {
    asm volatile("ldmatrix.sync.aligned.m8n8.x2.trans.shared.b16 {%0,%1}, [%2];"
                 : "=r"(r0), "=r"(r1) : "r"(addr));
}
__device__ __forceinline__ uint32_t bfpack(float lo, float hi) {
    __nv_bfloat162 t = __floats2bfloat162_rn(lo, hi);
    return *(uint32_t*)&t;
}
__device__ __forceinline__ void split2(float a0, float a1, uint32_t& hp, uint32_t& lp) {
    __nv_bfloat16 h0 = __float2bfloat16(a0), h1 = __float2bfloat16(a1);
    hp = (uint32_t)__bfloat16_as_ushort(h0) | ((uint32_t)__bfloat16_as_ushort(h1) << 16);
    lp = bfpack(a0 - __bfloat162float(h0), a1 - __bfloat162float(h1));
}

extern __shared__ char s_dyn[];

// ---------------------------------------------------------------------------
// K0: per (b,e) mention index lists
// ---------------------------------------------------------------------------
__global__ void k_build(const int* __restrict__ labels) {
    int b = blockIdx.x, e = threadIdx.x;
    int c = 0;
    int* lst = g_list + (b * EQ + e) * MQ;
    for (int m = 0; m < MQ; m++)
        if (labels[b * MQ + m] == e) lst[c++] = m;
    g_cnt[b * EQ + e] = c;
}

// ---------------------------------------------------------------------------
// K1: segment logsumexp over mentions -> ent_emb [B,E,H]
// ---------------------------------------------------------------------------
__global__ void k_ent_emb(const float* __restrict__ ent_lhs) {
    int be = blockIdx.x;
    int b = be / EQ;
    __shared__ int s_list[MQ];
    int cnt = g_cnt[be];
    for (int i = threadIdx.x; i < cnt; i += 256) s_list[i] = g_list[be * MQ + i];
    __syncthreads();
    const float* base = ent_lhs + (size_t)b * MQ * HQ;
    for (int h = threadIdx.x; h < HQ; h += 256) {
        float o = 0.f;
        if (cnt > 0) {
            float mx = -3.4e38f;
            for (int i = 0; i < cnt; i++) mx = fmaxf(mx, base[s_list[i] * HQ + h]);
            float s = 0.f;
            for (int i = 0; i < cnt; i++) s += expf(base[s_list[i] * HQ + h] - mx);
            o = mx + logf(s);
        }
        g_ent_emb[be * HQ + h] = o;
    }
}

// ---------------------------------------------------------------------------
// K2: mean mention attention -> ent_attn [B,E,NH,L]
// ---------------------------------------------------------------------------
__global__ void k_ent_attn(const float* __restrict__ attn) {
    int be = blockIdx.y, nh = blockIdx.x;
    int b = be / EQ;
    int cnt = g_cnt[be];
    __shared__ int s_list[MQ];
    for (int i = threadIdx.x; i < cnt; i += 128) s_list[i] = g_list[be * MQ + i];
    __syncthreads();
    float inv = (cnt > 0) ? 1.f / (float)cnt : 0.f;
    const float* abase = attn + ((size_t)(b * NHQ + nh)) * MQ * LQ;
    float* obase = g_ent_attn + ((size_t)(be * NHQ + nh)) * LQ;
    for (int l = threadIdx.x; l < LQ; l += 128) {
        float s = 0.f;
        for (int i = 0; i < cnt; i++) s += abase[s_list[i] * LQ + l];
        obase[l] = s * inv;
    }
}

// ---------------------------------------------------------------------------
// K3: pair attention product, mean over heads, normalize -> bf16 splits
// ---------------------------------------------------------------------------
__global__ void k_ht(const int* __restrict__ hts) {
    int n = blockIdx.x;
    int b = n / RQ;
    int he = hts[n * 2 + 0];
    int te = hts[n * 2 + 1];
    const float* ha = g_ent_attn + ((size_t)(b * EQ + he)) * NHQ * LQ;
    const float* ta = g_ent_attn + ((size_t)(b * EQ + te)) * NHQ * LQ;
    float v[4];
    float loc = 0.f;
#pragma unroll
    for (int rep = 0; rep < 4; rep++) {
        int l = threadIdx.x + rep * 128;
        float acc = 0.f;
#pragma unroll
        for (int nh = 0; nh < NHQ; nh++) acc += ha[nh * LQ + l] * ta[nh * LQ + l];
        v[rep] = acc * (1.0f / NHQ);
        loc += v[rep];
    }
    __shared__ float red[128];
    red[threadIdx.x] = loc;
    __syncthreads();
    for (int s = 64; s > 0; s >>= 1) {
        if (threadIdx.x < s) red[threadIdx.x] += red[threadIdx.x + s];
        __syncthreads();
    }
    float inv = 1.f / (red[0] + 1e-5f);
#pragma unroll
    for (int rep = 0; rep < 4; rep++) {
        int l = threadIdx.x + rep * 128;
        float val = v[rep] * inv;
        __nv_bfloat16 h = __float2bfloat16(val);
        g_hth[(size_t)n * LQ + l] = h;
        g_htl[(size_t)n * LQ + l] = __float2bfloat16(val - __bfloat162float(h));
    }
}

// ---------------------------------------------------------------------------
// K3b/K3c: bf16 hi/lo splits of seq and W bottom halves
// ---------------------------------------------------------------------------
__global__ void k_seqsplit(const float* __restrict__ seq) {
    int idx = blockIdx.x * 256 + threadIdx.x;
    if (idx >= BQ * LQ * HQ) return;
    float w = seq[idx];
    __nv_bfloat16 h = __float2bfloat16(w);
    g_seqh[idx] = h;
    g_seql[idx] = __float2bfloat16(w - __bfloat162float(h));
}

__global__ void k_wsplit(const float* __restrict__ Wh, const float* __restrict__ Wt) {
    int idx = blockIdx.x * 256 + threadIdx.x;
    if (idx >= 2 * HQ * DQ) return;
    int z = idx / (HQ * DQ);
    int r = idx - z * (HQ * DQ);
    float w = (z ? Wt : Wh)[(size_t)(HQ + r / DQ) * DQ + (r % DQ)];
    __nv_bfloat16 h = __float2bfloat16(w);
    g_Wsph[idx] = h;
    g_Wspl[idx] = __float2bfloat16(w - __bfloat162float(h));
}

// ---------------------------------------------------------------------------
// HMMA GEMM tiles: A [128 rows][32 k] pad-40 bf16 hi/lo, B [32 k][128 n]
// pad-136 bf16 hi/lo, double buffered. 8 warps, each 16 rows x 128 cols.
// ---------------------------------------------------------------------------
#define EA_STR 40
#define EB_STR 136
#define EA_SEG (128 * EA_STR)            // 5120 elems
#define EB_SEG (32 * EB_STR)             // 4352 elems
#define HG_SMEM ((4 * EA_SEG + 4 * EB_SEG) * 2)   // 75776 bytes

__device__ __forceinline__ void hg_load(uint4* pfA, uint4* pfB,
        const __nv_bfloat16* Ah_, const __nv_bfloat16* Al_, int astr,
        const __nv_bfloat16* Bh_, const __nv_bfloat16* Bl_, int bstr,
        int p0, int n0, int ks, int tid) {
#pragma unroll
    for (int q = 0; q < 4; q++) {
        int ch = tid + q * 256;          // 0..1023
        int sp = ch >> 9, idx = ch & 511;
        {
            int row = idx >> 2, c8 = idx & 3;
            const __nv_bfloat16* src = (sp ? Al_ : Ah_) +
                (size_t)(p0 + row) * astr + ks * 32 + c8 * 8;
            pfA[q] = *(const uint4*)src;
        }
        {
            int kr = idx >> 4, c8 = idx & 15;
            const __nv_bfloat16* src = (sp ? Bl_ : Bh_) +
                (size_t)(ks * 32 + kr) * bstr + n0 + c8 * 8;
            pfB[q] = *(const uint4*)src;
        }
    }
}

__device__ __forceinline__ void hg_store(const uint4* pfA, const uint4* pfB,
        __nv_bfloat16* As, __nv_bfloat16* Bs, int st, int tid) {
#pragma unroll
    for (int q = 0; q < 4; q++) {
        int ch = tid + q * 256;
        int sp = ch >> 9, idx = ch & 511;
        {
            int row = idx >> 2, c8 = idx & 3;
            *(uint4*)(As + (st * 2 + sp) * EA_SEG + row * EA_STR + c8 * 8) = pfA[q];
        }
        {
            int kr = idx >> 4, c8 = idx & 15;
            *(uint4*)(Bs + (st * 2 + sp) * EB_SEG + kr * EB_STR + c8 * 8) = pfB[q];
        }
    }
}

__device__ __forceinline__ void hg_compute(float* acc, const __nv_bfloat16* As,
        __nv_bfloat16* Bs, int st, int rA, int rB, int ko, int lane) {
    const __nv_bfloat16* Ah = As + (st * 2 + 0) * EA_SEG;
    const __nv_bfloat16* Al = As + (st * 2 + 1) * EA_SEG;
    uint32_t bh_base = smem_u32(Bs + (st * 2 + 0) * EB_SEG);
    uint32_t bl_base = smem_u32(Bs + (st * 2 + 1) * EB_SEG);
#pragma unroll
    for (int kc = 0; kc < 32; kc += 16) {
        uint32_t ah0 = *(const uint32_t*)(Ah + rA * EA_STR + kc + ko);
        uint32_t ah1 = *(const uint32_t*)(Ah + rB * EA_STR + kc + ko);
        uint32_t ah2 = *(const uint32_t*)(Ah + rA * EA_STR + kc + 8 + ko);
        uint32_t ah3 = *(const uint32_t*)(Ah + rB * EA_STR + kc + 8 + ko);
        uint32_t al0 = *(const uint32_t*)(Al + rA * EA_STR + kc + ko);
        uint32_t al1 = *(const uint32_t*)(Al + rB * EA_STR + kc + ko);
        uint32_t al2 = *(const uint32_t*)(Al + rA * EA_STR + kc + 8 + ko);
        uint32_t al3 = *(const uint32_t*)(Al + rB * EA_STR + kc + 8 + ko);
        uint32_t bh = bh_base + (kc + (lane & 15)) * (EB_STR * 2);
        uint32_t bl = bl_base + (kc + (lane & 15)) * (EB_STR * 2);
#pragma unroll
        for (int t = 0; t < 16; t++) {
            uint32_t b0, b1, c0, c1;
            ldsm2t(b0, b1, bh + t * 16);
            ldsm2t(c0, c1, bl + t * 16);
            mma16816(acc + t * 4, ah0, ah1, ah2, ah3, b0, b1);
            mma16816(acc + t * 4, ah0, ah1, ah2, ah3, c0, c1);
            mma16816(acc + t * 4, al0, al1, al2, al3, b0, b1);
        }
    }
}

// ---------------------------------------------------------------------------
// K4: rel = ht @ seq  (HMMA 3-split)  M=4096 N=1024 K=512, epilogue -> splits
// ---------------------------------------------------------------------------
__global__ __launch_bounds__(256) void gemm_rel_hmma() {
    __nv_bfloat16* As = (__nv_bfloat16*)s_dyn;
    __nv_bfloat16* Bs = (__nv_bfloat16*)s_dyn + 4 * EA_SEG;
    int tid = threadIdx.x, lane = tid & 31, wid = tid >> 5;
    int n0 = blockIdx.x * 128, p0 = blockIdx.y * 128;
    int b = p0 >> 10;
    const __nv_bfloat16* Bh_ = g_seqh + (size_t)b * LQ * HQ;
    const __nv_bfloat16* Bl_ = g_seql + (size_t)b * LQ * HQ;
    // p0 is a global pair row; A rows index g_hth directly (batch-flattened)
    uint4 pfA[4], pfB[4];
    hg_load(pfA, pfB, g_hth, g_htl, LQ, Bh_, Bl_, HQ, p0, n0, 0, tid);
    hg_store(pfA, pfB, As, Bs, 0, tid);
    __syncthreads();

    float acc[64];
#pragma unroll
    for (int t = 0; t < 64; t++) acc[t] = 0.f;
    int rA = wid * 16 + (lane >> 2), rB = rA + 8, ko = (lane & 3) * 2;

    for (int ks = 0; ks < 16; ks++) {
        int st = ks & 1;
        if (ks + 1 < 16)
            hg_load(pfA, pfB, g_hth, g_htl, LQ, Bh_, Bl_, HQ, p0, n0, ks + 1, tid);
        hg_compute(acc, As, Bs, st, rA, rB, ko, lane);
        __syncthreads();
        if (ks + 1 < 16) hg_store(pfA, pfB, As, Bs, st ^ 1, tid);
        __syncthreads();
    }

    int nA = p0 + rA, nB = p0 + rB;
#pragma unroll
    for (int t = 0; t < 16; t++) {
        int col = n0 + t * 8 + (lane & 3) * 2;
        uint32_t hp, lp;
        split2(acc[t * 4 + 0], acc[t * 4 + 1], hp, lp);
        *(uint32_t*)&g_relh[(size_t)nA * HQ + col] = hp;
        *(uint32_t*)&g_rell[(size_t)nA * HQ + col] = lp;
        split2(acc[t * 4 + 2], acc[t * 4 + 3], hp, lp);
        *(uint32_t*)&g_relh[(size_t)nB * HQ + col] = hp;
        *(uint32_t*)&g_rell[(size_t)nB * HQ + col] = lp;
    }
}

// ---------------------------------------------------------------------------
// K5a: entW[z, be, :] = ent_emb[be] @ W_top + bias   (f32x2, tiny)
// ---------------------------------------------------------------------------
__global__ __launch_bounds__(256) void gemm_ent(
    const float* __restrict__ Wh, const float* __restrict__ bh,
    const float* __restrict__ Wt, const float* __restrict__ bt) {
    int z = blockIdx.z;
    int n0 = blockIdx.x * 128;
    int r0 = blockIdx.y * 128;
    const float* W = z ? Wt : Wh;
    const float* bias = z ? bt : bh;

    __shared__ float As[16][128];
    __shared__ float Bsh[16][128];
    int tid = threadIdx.x;
    u64t acc2[8][4];
#pragma unroll
    for (int i = 0; i < 8; i++)
#pragma unroll
        for (int j = 0; j < 4; j++) acc2[i][j] = 0ULL;

    int arow = tid >> 1, akc = (tid & 1) * 8;
    int brow = tid >> 4, bcc = (tid & 15) * 8;
    int rm = (tid >> 4) * 8, rn = (tid & 15) * 8;
    const float* Abase = g_ent_emb + (size_t)r0 * HQ;

    for (int k0 = 0; k0 < HQ; k0 += 16) {
        float4 a0 = *(const float4*)(Abase + (size_t)arow * HQ + k0 + akc);
        float4 a1 = *(const float4*)(Abase + (size_t)arow * HQ + k0 + akc + 4);
        float4 b0 = *(const float4*)(W + (size_t)(k0 + brow) * DQ + n0 + bcc);
        float4 b1 = *(const float4*)(W + (size_t)(k0 + brow) * DQ + n0 + bcc + 4);
        __syncthreads();
        As[akc + 0][arow] = a0.x; As[akc + 1][arow] = a0.y;
        As[akc + 2][arow] = a0.z; As[akc + 3][arow] = a0.w;
        As[akc + 4][arow] = a1.x; As[akc + 5][arow] = a1.y;
        As[akc + 6][arow] = a1.z; As[akc + 7][arow] = a1.w;
        *(float4*)&Bsh[brow][bcc] = b0;
        *(float4*)&Bsh[brow][bcc + 4] = b1;
        __syncthreads();
#pragma unroll
        for (int kk = 0; kk < 16; kk++) {
            float a[8];
            *(float4*)&a[0] = *(const float4*)&As[kk][rm];
            *(float4*)&a[4] = *(const float4*)&As[kk][rm + 4];
            ulonglong2 bu0 = *(const ulonglong2*)&Bsh[kk][rn];
            ulonglong2 bu1 = *(const ulonglong2*)&Bsh[kk][rn + 4];
            u64t b2[4] = {bu0.x, bu0.y, bu1.x, bu1.y};
#pragma unroll
            for (int i = 0; i < 8; i++) {
                u64t a2 = pack2b(a[i]);
#pragma unroll
                for (int j = 0; j < 4; j++) fma2(acc2[i][j], a2, b2[j]);
            }
        }
    }
    float* Cb = g_entW + ((size_t)z * NEQ + r0) * DQ + n0;
#pragma unroll
    for (int i = 0; i < 8; i++)
#pragma unroll
        for (int j = 0; j < 4; j++) {
            float2 v = unpack2(acc2[i][j]);
            int col = rn + 2 * j;
            Cb[(size_t)(rm + i) * DQ + col]     = v.x + bias[n0 + col];
            Cb[(size_t)(rm + i) * DQ + col + 1] = v.y + bias[n0 + col + 1];
        }
}

// ---------------------------------------------------------------------------
// K5b: hv/tv = tanh(rel @ W_bot + gathered entW)  (HMMA 3-split)
// M=4096 N=768 K=1024, z=0/1
// ---------------------------------------------------------------------------
__global__ __launch_bounds__(256) void gemm_extract_hmma(const int* __restrict__ hts) {
    __nv_bfloat16* As = (__nv_bfloat16*)s_dyn;
    __nv_bfloat16* Bs = (__nv_bfloat16*)s_dyn + 4 * EA_SEG;
    int tid = threadIdx.x, lane = tid & 31, wid = tid >> 5;
    int z = blockIdx.z, n0 = blockIdx.x * 128, p0 = blockIdx.y * 128;
    const __nv_bfloat16* Bh_ = g_Wsph + (size_t)z * HQ * DQ;
    const __nv_bfloat16* Bl_ = g_Wspl + (size_t)z * HQ * DQ;

    uint4 pfA[4], pfB[4];
    hg_load(pfA, pfB, g_relh, g_rell, HQ, Bh_, Bl_, DQ, p0, n0, 0, tid);
    hg_store(pfA, pfB, As, Bs, 0, tid);
    __syncthreads();

    float acc[64];
#pragma unroll
    for (int t = 0; t < 64; t++) acc[t] = 0.f;
    int rA = wid * 16 + (lane >> 2), rB = rA + 8, ko = (lane & 3) * 2;

    for (int ks = 0; ks < 32; ks++) {
        int st = ks & 1;
        if (ks + 1 < 32)
            hg_load(pfA, pfB, g_relh, g_rell, HQ, Bh_, Bl_, DQ, p0, n0, ks + 1, tid);
        hg_compute(acc, As, Bs, st, rA, rB, ko, lane);
        __syncthreads();
        if (ks + 1 < 32) hg_store(pfA, pfB, As, Bs, st ^ 1, tid);
        __syncthreads();
    }

    int nA = p0 + rA, nB = p0 + rB;
    int eA = hts[nA * 2 + z], eB = hts[nB * 2 + z];
    const float* ewA = g_entW + ((size_t)z * NEQ + (nA >> 10) * EQ + eA) * DQ + n0;
    const float* ewB = g_entW + ((size_t)z * NEQ + (nB >> 10) * EQ + eB) * DQ + n0;
    float* C = z ? g_tv : g_hv;
#pragma unroll
    for (int t = 0; t < 16; t++) {
        int col = t * 8 + (lane & 3) * 2;
        float2 vA, vB;
        vA.x = tanhf(acc[t * 4 + 0] + ewA[col]);
        vA.y = tanhf(acc[t * 4 + 1] + ewA[col + 1]);
        vB.x = tanhf(acc[t * 4 + 2] + ewB[col]);
        vB.y = tanhf(acc[t * 4 + 3] + ewB[col + 1]);
        *(float2*)&C[(size_t)nA * DQ + n0 + col] = vA;
        *(float2*)&C[(size_t)nB * DQ + n0 + col] = vB;
    }
}

// ---------------------------------------------------------------------------
// K6a: transpose-to-k-major + bf16 hi/lo split of Wb -> g_WbB_h/l [KTOT][128]
// ---------------------------------------------------------------------------
__global__ void k_wbt(const float* __restrict__ Wb) {
    int idx = blockIdx.x * 256 + threadIdx.x;
    if (idx >= KTOT * 128) return;
    int k = idx >> 7;
    int n = idx & 127;
    float w = (n < CQ) ? Wb[(size_t)k * CQ + n] : 0.f;
    __nv_bfloat16 wh = __float2bfloat16(w);
    float r = w - __bfloat162float(wh);
    g_WbB_h[idx] = wh;
    g_WbB_l[idx] = __float2bfloat16(r);
}

// ---------------------------------------------------------------------------
// K6b: final block-bilinear GEMM on HMMA (bf16 3-split, f32 accum).
// ---------------------------------------------------------------------------
#define BSTR 136
#define BTILE (64 * BSTR)

__device__ __forceinline__ void load_pf(uint4* pf, int kb, int i, int tid) {
    size_t kbase = ((size_t)kb * 4096 + (size_t)i * 64) * 128;
#pragma unroll
    for (int q = 0; q < 8; q++) {
        int ch = tid + q * 256;
        int split = ch >> 10;
        int idx = ch & 1023;
        const __nv_bfloat16* src = (split ? g_WbB_l : g_WbB_h) + kbase + (size_t)idx * 8;
        pf[q] = *(const uint4*)src;
    }
}

__device__ __forceinline__ void store_pf(const uint4* pf, __nv_bfloat16* Bbuf,
                                         int st, int tid) {
#pragma unroll
    for (int q = 0; q < 8; q++) {
        int ch = tid + q * 256;
        int split = ch >> 10;
        int idx = ch & 1023;
        int row = idx >> 4, col8 = idx & 15;
        *(uint4*)(Bbuf + (size_t)(st * 2 + split) * BTILE + row * BSTR + col8 * 8) = pf[q];
    }
}

__global__ __launch_bounds__(256, 1) void gemm_final_hmma() {
    float* hv_s = (float*)s_dyn;                          // [128][64]
    __nv_bfloat16* Bbuf = (__nv_bfloat16*)(s_dyn + 32768);
    int tid = threadIdx.x, lane = tid & 31, wid = tid >> 5;
    int p0 = blockIdx.x * 128;
    int kb = blockIdx.y;

    for (int t = tid; t < 128 * 64; t += 256) {
        int r = t >> 6, c = t & 63;
        hv_s[t] = g_hv[(size_t)(p0 + r) * DQ + kb * 64 + c];
    }

    int rA = wid * 16 + (lane >> 2), rB = rA + 8;
    float tvA[16], tvB[16];
    {
        const float* tA = g_tv + (size_t)(p0 + rA) * DQ + kb * 64;
        const float* tB = g_tv + (size_t)(p0 + rB) * DQ + kb * 64;
#pragma unroll
        for (int c = 0; c < 4; c++) {
            int j0 = c * 16 + (lane & 3) * 2;
            tvA[c * 4 + 0] = tA[j0];     tvA[c * 4 + 1] = tA[j0 + 1];
            tvA[c * 4 + 2] = tA[j0 + 8]; tvA[c * 4 + 3] = tA[j0 + 9];
            tvB[c * 4 + 0] = tB[j0];     tvB[c * 4 + 1] = tB[j0 + 1];
            tvB[c * 4 + 2] = tB[j0 + 8]; tvB[c * 4 + 3] = tB[j0 + 9];
        }
    }

    uint4 pf[8];
    load_pf(pf, kb, 0, tid);
    store_pf(pf, Bbuf, 0, tid);
    __syncthreads();

    float acc[64];
#pragma unroll
    for (int t = 0; t < 64; t++) acc[t] = 0.f;

    for (int i = 0; i < 64; i++) {
        int st = i & 1;
        if (i + 1 < 64) load_pf(pf, kb, i + 1, tid);

        float hA = hv_s[rA * 64 + i];
        float hB = hv_s[rB * 64 + i];

#pragma unroll
        for (int c = 0; c < 4; c++) {
            float pA0 = hA * tvA[c * 4 + 0], pA1 = hA * tvA[c * 4 + 1];
            float pA2 = hA * tvA[c * 4 + 2], pA3 = hA * tvA[c * 4 + 3];
            float pB0 = hB * tvB[c * 4 + 0], pB1 = hB * tvB[c * 4 + 1];
            float pB2 = hB * tvB[c * 4 + 2], pB3 = hB * tvB[c * 4 + 3];
            uint32_t ah0 = bfpack(pA0, pA1), ah1 = bfpack(pB0, pB1);
            uint32_t ah2 = bfpack(pA2, pA3), ah3 = bfpack(pB2, pB3);
            float rA0 = pA0 - __bfloat162float(__float2bfloat16(pA0));
            float rA1 = pA1 - __bfloat162float(__float2bfloat16(pA1));
            float rA2 = pA2 - __bfloat162float(__float2bfloat16(pA2));
            float rA3 = pA3 - __bfloat162float(__float2bfloat16(pA3));
            float rB0 = pB0 - __bfloat162float(__float2bfloat16(pB0));
            float rB1 = pB1 - __bfloat162float(__float2bfloat16(pB1));
            float rB2 = pB2 - __bfloat162float(__float2bfloat16(pB2));
            float rB3 = pB3 - __bfloat162float(__float2bfloat16(pB3));
            uint32_t al0 = bfpack(rA0, rA1), al1 = bfpack(rB0, rB1);
            uint32_t al2 = bfpack(rA2, rA3), al3 = bfpack(rB2, rB3);

            int brow = c * 16 + (lane & 15);
            uint32_t base_h = smem_u32(Bbuf + (size_t)(st * 2 + 0) * BTILE + brow * BSTR);
            uint32_t base_l = smem_u32(Bbuf + (size_t)(st * 2 + 1) * BTILE + brow * BSTR);

#pragma unroll
            for (int t = 0; t < 16; t++) {
                uint32_t bh0, bh1, bl0, bl1;
                ldsm2t(bh0, bh1, base_h + t * 16);
                ldsm2t(bl0, bl1, base_l + t * 16);
                mma16816(acc + t * 4, ah0, ah1, ah2, ah3, bh0, bh1);
                mma16816(acc + t * 4, ah0, ah1, ah2, ah3, bl0, bl1);
                mma16816(acc + t * 4, al0, al1, al2, al3, bh0, bh1);
            }
        }
        __syncthreads();
        if (i + 1 < 64) store_pf(pf, Bbuf, st ^ 1, tid);
        __syncthreads();
    }

    float* P = g_part + (size_t)kb * NP * CQ;
#pragma unroll
    for (int t = 0; t < 16; t++) {
        int col = t * 8 + (lane & 3) * 2;
        if (col < CQ) {
            P[(size_t)(p0 + rA) * CQ + col] = acc[t * 4 + 0];
            P[(size_t)(p0 + rB) * CQ + col] = acc[t * 4 + 2];
            if (col + 1 < CQ) {
                P[(size_t)(p0 + rA) * CQ + col + 1] = acc[t * 4 + 1];
                P[(size_t)(p0 + rB) * CQ + col + 1] = acc[t * 4 + 3];
            }
        }
    }
}

// ---------------------------------------------------------------------------
// K7: deterministic split-K reduction + bias
// ---------------------------------------------------------------------------
__global__ void k_reduce(const float* __restrict__ bbias, float* __restrict__ out) {
    int idx = blockIdx.x * 256 + threadIdx.x;
    if (idx < NP * CQ) {
        int c = idx % CQ;
        float s = bbias[c];
#pragma unroll
        for (int z = 0; z < NKB; z++) s += g_part[(size_t)z * NP * CQ + idx];
        out[idx] = s;
    }
}

// ---------------------------------------------------------------------------
extern "C" void kernel_launch(void* const* d_in, const int* in_sizes, int n_in,
                              void* d_out, int out_size) {
    const float* seq     = (const float*)d_in[0];   // [B,L,H]
    const float* ent_lhs = (const float*)d_in[1];   // [B,M,H]
    const float* attn    = (const float*)d_in[2];   // [B,NH,M,L]
    const int*   labels  = (const int*)d_in[3];     // [B,M]
    const int*   hts     = (const int*)d_in[4];     // [B,R,2]
    const float* Wh      = (const float*)d_in[5];   // [2H,D]
    const float* bh      = (const float*)d_in[6];   // [D]
    const float* Wt      = (const float*)d_in[7];
    const float* bt      = (const float*)d_in[8];
    const float* Wb      = (const float*)d_in[9];   // [D*BLK,C]
    const float* bbias   = (const float*)d_in[10];  // [C]
    float* out = (float*)d_out;

    const int FIN_SMEM = 32768 + 4 * BTILE * 2;     // 102400 bytes
    cudaFuncSetAttribute(gemm_final_hmma,
                         cudaFuncAttributeMaxDynamicSharedMemorySize, FIN_SMEM);
    cudaFuncSetAttribute(gemm_rel_hmma,
                         cudaFuncAttributeMaxDynamicSharedMemorySize, HG_SMEM);
    cudaFuncSetAttribute(gemm_extract_hmma,
                         cudaFuncAttributeMaxDynamicSharedMemorySize, HG_SMEM);

    k_build<<<BQ, EQ>>>(labels);
    k_ent_emb<<<NEQ, 256>>>(ent_lhs);
    k_ent_attn<<<dim3(NHQ, NEQ), 128>>>(attn);
    k_ht<<<NP, 128>>>(hts);
    k_seqsplit<<<(BQ * LQ * HQ + 255) / 256, 256>>>(seq);
    k_wsplit<<<(2 * HQ * DQ + 255) / 256, 256>>>(Wh, Wt);
    k_wbt<<<(KTOT * 128 + 255) / 256, 256>>>(Wb);
    gemm_rel_hmma<<<dim3(HQ / 128, NP / 128), 256, HG_SMEM>>>();
    gemm_ent<<<dim3(DQ / 128, NEQ / 128, 2), 256>>>(Wh, bh, Wt, bt);
    gemm_extract_hmma<<<dim3(DQ / 128, NP / 128, 2), 256, HG_SMEM>>>(hts);
    gemm_final_hmma<<<dim3(NP / 128, NKB), 256, FIN_SMEM>>>();
    k_reduce<<<(NP * CQ + 255) / 256, 256>>>(bbias, out);
}